// round 13
// baseline (speedup 1.0000x reference)
#include <cuda_runtime.h>
#include <cuda_bf16.h>
#include <math_constants.h>
#include <cstdint>

// Problem constants (fixed by the dataset)
#define NN   50000
#define EE   600000
#define EP   (EE + NN)     // edges + self loops = 650000
#define FIN  128
#define HC   256           // H*C = 4*64
#define NG   64            // graphs
#define NCLS 3

#define SMEM_SWIZZLE_128B(b) ((b) ^ (((b) >> 3) & 0x70))

__device__ __forceinline__ uint32_t smem_to_u32(const void* p) {
    uint32_t a;
    asm("{ .reg .u64 t; cvta.to.shared.u64 t, %1; cvt.u32.u64 %0, t; }" : "=r"(a) : "l"(p));
    return a;
}
__device__ __forceinline__ void cp_async16(uint32_t dst, const void* src, bool pred) {
    int sz = pred ? 16 : 0;
    asm volatile("cp.async.cg.shared.global [%0], [%1], 16, %2;"
                 :: "r"(dst), "l"(src), "r"(sz) : "memory");
}
template <int N>
__device__ __forceinline__ void cp_async_wait() {
    asm volatile("cp.async.wait_group %0;" :: "n"(N) : "memory");
}
__device__ __forceinline__ void ldsm_x4(uint32_t* r, uint32_t addr) {
    asm volatile("ldmatrix.sync.aligned.m8n8.x4.shared.b16 {%0,%1,%2,%3}, [%4];"
                 : "=r"(r[0]), "=r"(r[1]), "=r"(r[2]), "=r"(r[3]) : "r"(addr));
}
__device__ __forceinline__ void mma16816(float* c, const uint32_t* a, const uint32_t* b) {
    asm volatile("mma.sync.aligned.m16n8k16.row.col.f32.bf16.bf16.f32 "
                 "{%0,%1,%2,%3}, {%4,%5,%6,%7}, {%8,%9}, {%0,%1,%2,%3};"
                 : "+f"(c[0]), "+f"(c[1]), "+f"(c[2]), "+f"(c[3])
                 : "r"(a[0]), "r"(a[1]), "r"(a[2]), "r"(a[3]), "r"(b[0]), "r"(b[1]));
}

// ---------------- device scratch (no allocation allowed) ----------------
__device__ float g_XL[(size_t)NN * HC];
__device__ float g_XR[(size_t)NN * HC];
__device__ float g_H [(size_t)NN * HC];
__device__ __align__(16) __nv_bfloat16 g_Ab[(size_t)NN * 512];  // A [hi|lo], stride 2K
__device__ __align__(16) __nv_bfloat16 g_Wb0[512 * 128];        // layer0 B = Whi only, [n][K]
__device__ __align__(16) __nv_bfloat16 g_Wb1[512 * 256];        // layer1 B = Whi only
__device__ __align__(16) __nv_bfloat16 g_Wb2[512 * 256];        // layer2 B = Whi only
__device__ int   g_deg[NN];
__device__ int   g_off[NN];
__device__ int   g_cur[NN];
__device__ int   g_esrc[EP];
__device__ int   g_bsum[64];
__device__ int   g_bsumex[64];
__device__ float    g_psum[NG * HC];
__device__ unsigned g_pmax[NG * HC];
__device__ int      g_cnt[NG];

__device__ __forceinline__ unsigned fkey(float f) {
    unsigned b = __float_as_uint(f);
    return (b & 0x80000000u) ? ~b : (b | 0x80000000u);
}
__device__ __forceinline__ float fdekey(unsigned u) {
    return (u & 0x80000000u) ? __uint_as_float(u & 0x7FFFFFFFu) : __uint_as_float(~u);
}

// ---------------- fused prologue: convA | convW | init ----------------
#define PB_A 6250                    // convA: NN*FIN/4 / 256
#define PB_W (PB_A + 1536)           // convW: 6 matrices x 256 blocks
#define PB_I (PB_W + 256)            // init
__global__ void k_prep(const float* __restrict__ x,
                       const float* __restrict__ Wl0, const float* __restrict__ Wr0,
                       const float* __restrict__ Wl1, const float* __restrict__ Wr1,
                       const float* __restrict__ Wl2, const float* __restrict__ Wr2) {
    int b = blockIdx.x, tid = threadIdx.x;
    if (b < PB_A) {
        // convA: fp32 -> bf16 [hi|lo], stride 256
        int i = b * 256 + tid;
        if (i >= NN * FIN / 4) return;
        int row = i >> 5, j = (i & 31) * 4;
        float4 v = ((const float4*)x)[i];
        __nv_bfloat16 hx = __float2bfloat16(v.x), hy = __float2bfloat16(v.y);
        __nv_bfloat16 hz = __float2bfloat16(v.z), hw = __float2bfloat16(v.w);
        __nv_bfloat162 h01(hx, hy), h23(hz, hw);
        __nv_bfloat162 l01(__float2bfloat16(v.x - __bfloat162float(hx)),
                           __float2bfloat16(v.y - __bfloat162float(hy)));
        __nv_bfloat162 l23(__float2bfloat16(v.z - __bfloat162float(hz)),
                           __float2bfloat16(v.w - __bfloat162float(hw)));
        size_t base = (size_t)row * 256;
        *(__nv_bfloat162*)&g_Ab[base + j]           = h01;
        *(__nv_bfloat162*)&g_Ab[base + j + 2]       = h23;
        *(__nv_bfloat162*)&g_Ab[base + 128 + j]     = l01;
        *(__nv_bfloat162*)&g_Ab[base + 128 + j + 2] = l23;
    } else if (b < PB_W) {
        // convW: W [K][256] fp32 -> dst[n][K] bf16 (hi)
        int bb = b - PB_A;
        int y = bb >> 8;
        int K = (y < 2) ? FIN : HC;
        int i = (bb & 255) * 256 + tid;
        if (i >= K * 256) return;
        const float* W;
        __nv_bfloat16* dst;
        switch (y) {
            case 0: W = Wl0; dst = g_Wb0; break;
            case 1: W = Wr0; dst = g_Wb0; break;
            case 2: W = Wl1; dst = g_Wb1; break;
            case 3: W = Wr1; dst = g_Wb1; break;
            case 4: W = Wl2; dst = g_Wb2; break;
            default: W = Wr2; dst = g_Wb2; break;
        }
        int nbase = (y & 1) * 256;
        int k = i >> 8, n = i & 255;
        dst[(size_t)(nbase + n) * K + k] = __float2bfloat16(W[i]);
    } else {
        // init: deg/psum/pmax/cnt
        int i = (b - PB_W) * 256 + tid;
        int stride = 256 * 256;
        for (int j = i; j < NN; j += stride) g_deg[j] = 0;
        for (int j = i; j < NG * HC; j += stride) { g_psum[j] = 0.f; g_pmax[j] = 0x007FFFFFu; }
        for (int j = i; j < NG; j += stride) g_cnt[j] = 0;
    }
}

// deg histogram + graph counts (after k_prep's init has completed)
__global__ void k_deg(const int* __restrict__ ei, const int* __restrict__ batch) {
    int i = blockIdx.x * blockDim.x + threadIdx.x;
    if (i < NN) atomicAdd(&g_cnt[batch[i]], 1);
    if (i >= EP) return;
    int d = (i < EE) ? ei[EE + i] : (i - EE);
    atomicAdd(&g_deg[d], 1);
}

// ---------------- 3-phase scan ----------------
__global__ void k_scan1() {
    __shared__ int wsum[32];
    int b = blockIdx.x, tid = threadIdx.x, lane = tid & 31, wid = tid >> 5;
    int i = b * 1024 + tid;
    int v = (i < NN) ? g_deg[i] : 0;
    int x = v;
    #pragma unroll
    for (int o = 1; o < 32; o <<= 1) {
        int t = __shfl_up_sync(0xFFFFFFFFu, x, o);
        if (lane >= o) x += t;
    }
    if (lane == 31) wsum[wid] = x;
    __syncthreads();
    if (wid == 0) {
        int orig = wsum[lane];
        int y = orig;
        #pragma unroll
        for (int o = 1; o < 32; o <<= 1) {
            int t = __shfl_up_sync(0xFFFFFFFFu, y, o);
            if (lane >= o) y += t;
        }
        wsum[lane] = y - orig;
    }
    __syncthreads();
    int incl = x + wsum[wid];
    if (i < NN) g_off[i] = incl - v;
    if (tid == 1023) g_bsum[b] = incl;
}

__global__ void k_scan2(int nblocks) {
    __shared__ int s[64];
    int tid = threadIdx.x;
    s[tid] = (tid < nblocks) ? g_bsum[tid] : 0;
    __syncthreads();
    #pragma unroll
    for (int o = 1; o < 64; o <<= 1) {
        int t = (tid >= o) ? s[tid - o] : 0;
        __syncthreads();
        s[tid] += t;
        __syncthreads();
    }
    if (tid < nblocks) g_bsumex[tid] = s[tid] - g_bsum[tid];
}

__global__ void k_scan3() {
    int i = blockIdx.x * blockDim.x + threadIdx.x;
    if (i >= NN) return;
    int off = g_off[i] + g_bsumex[i >> 10];
    g_off[i] = off;
    g_cur[i] = off;
}

__global__ void k_scatter(const int* __restrict__ ei) {
    int i = blockIdx.x * blockDim.x + threadIdx.x;
    if (i >= EP) return;
    int s, d;
    if (i < EE) { s = ei[i]; d = ei[EE + i]; }
    else        { s = d = i - EE; }
    int pos = atomicAdd(&g_cur[d], 1);
    g_esrc[pos] = s;
}

// ---------------- mma.sync bf16 GEMM ----------------
// CTA tile 128 x 128, 256 threads = 8 warps (4M x 2N), warp tile 32x64.
// 3-stage cp.async pipeline, K-chunk 64. 2 CTAs/SM.
// 2-term split: D = Ahi*Bhi + Alo*Bhi. Logical K = KLOG = 2K.
#define A_BYTES (128 * 64 * 2)   // 16KB
#define B_BYTES (128 * 64 * 2)   // 16KB
#define GEMM_SMEM (3 * (A_BYTES + B_BYTES))   // 96KB

template <int KLOG, int KB>
__global__ void __launch_bounds__(256, 2) k_gemm(int wsel,
                                                 const float* __restrict__ biasL,
                                                 const float* __restrict__ biasR) {
    extern __shared__ char smem[];
    const __nv_bfloat16* Wb = (wsel == 0) ? g_Wb0 : (wsel == 1) ? g_Wb1 : g_Wb2;
    const int tid = threadIdx.x;
    const int lane = tid & 31, wid = tid >> 5;
    const int m0 = blockIdx.x * 128;
    const int n0 = blockIdx.y * 128;
    const int wm = (wid & 3) * 32;
    const int wn = (wid >> 2) * 64;

    uint32_t sbase = smem_to_u32(smem);

    float acc[2][8][4];
    #pragma unroll
    for (int mt = 0; mt < 2; mt++)
        #pragma unroll
        for (int nt = 0; nt < 8; nt++)
            #pragma unroll
            for (int q = 0; q < 4; q++) acc[mt][nt][q] = 0.f;

    constexpr int NT = KLOG / 64;

    auto issue = [&](int slot, int c) {
        uint32_t ab = sbase + slot * A_BYTES;
        uint32_t bb = sbase + 3 * A_BYTES + slot * B_BYTES;
        int ka = c * 64;
        int kb = (c * 64) & (KB - 1);
        #pragma unroll
        for (int i = 0; i < 4; i++) {
            int chunk = tid + i * 256;
            int row = chunk >> 3, seg = chunk & 7;
            int sw = SMEM_SWIZZLE_128B(row * 128 + seg * 16);
            bool ok = (m0 + row) < NN;
            int grow = ok ? (m0 + row) : 0;
            cp_async16(ab + sw, &g_Ab[(size_t)grow * KLOG + ka + seg * 8], ok);
        }
        #pragma unroll
        for (int i = 0; i < 4; i++) {
            int chunk = tid + i * 256;
            int row = chunk >> 3, seg = chunk & 7;
            int sw = SMEM_SWIZZLE_128B(row * 128 + seg * 16);
            cp_async16(bb + sw, &Wb[(size_t)(n0 + row) * KB + kb + seg * 8], true);
        }
        asm volatile("cp.async.commit_group;" ::: "memory");
    };

    issue(0, 0);
    issue(1, 1);

    for (int t = 0; t < NT; t++) {
        if (t + 1 < NT) cp_async_wait<1>(); else cp_async_wait<0>();
        __syncthreads();
        if (t + 2 < NT) issue((t + 2) % 3, t + 2);

        int slot = t % 3;
        uint32_t ab = sbase + slot * A_BYTES;
        uint32_t bb = sbase + 3 * A_BYTES + slot * B_BYTES;
        #pragma unroll
        for (int ks = 0; ks < 4; ks++) {
            int k16 = ks * 16;
            uint32_t a[2][4];
            #pragma unroll
            for (int mt = 0; mt < 2; mt++) {
                int row = wm + mt * 16 + (lane & 15);
                int col = k16 + (lane >> 4) * 8;
                ldsm_x4(a[mt], ab + SMEM_SWIZZLE_128B(row * 128 + col * 2));
            }
            uint32_t b[4][4];
            #pragma unroll
            for (int nt = 0; nt < 4; nt++) {
                int row = wn + nt * 16 + (lane & 7) + ((lane >> 4) << 3);
                int col = k16 + ((lane >> 3) & 1) * 8;
                ldsm_x4(b[nt], bb + SMEM_SWIZZLE_128B(row * 128 + col * 2));
            }
            #pragma unroll
            for (int mt = 0; mt < 2; mt++)
                #pragma unroll
                for (int nt = 0; nt < 8; nt++)
                    mma16816(acc[mt][nt], a[mt], &b[nt >> 1][(nt & 1) * 2]);
        }
    }

    // epilogue: bias add + split XL/XR
    bool halfR = (n0 + wn) >= 256;
    float* outp = halfR ? g_XR : g_XL;
    const float* bias = halfR ? biasR : biasL;
    int cb = n0 + wn - (halfR ? 256 : 0);
    #pragma unroll
    for (int mt = 0; mt < 2; mt++) {
        int r0 = m0 + wm + mt * 16 + (lane >> 2);
        #pragma unroll
        for (int nt = 0; nt < 8; nt++) {
            int c = cb + nt * 8 + (lane & 3) * 2;
            float b0 = bias[c], b1 = bias[c + 1];
            if (r0 < NN)
                *(float2*)&outp[(size_t)r0 * HC + c] =
                    make_float2(acc[mt][nt][0] + b0, acc[mt][nt][1] + b1);
            if (r0 + 8 < NN)
                *(float2*)&outp[(size_t)(r0 + 8) * HC + c] =
                    make_float2(acc[mt][nt][2] + b0, acc[mt][nt][3] + b1);
        }
    }
}

// ---------------- warp-per-node edge softmax + aggregation ----------------
// Round-8 compute shape + 2-stage load pipeline: next pair's gathers issue
// before current pair's compute, hiding L2 latency. Same math order.
template <bool PACK>
__global__ void k_agg(const float* __restrict__ att, const float* __restrict__ bias) {
    int gt = blockIdx.x * blockDim.x + threadIdx.x;
    int node = gt >> 5;
    int lane = gt & 31;
    if (node >= NN) return;

    int fb = lane * 8;

    float4 x0 = *(const float4*)&g_XR[(size_t)node * HC + fb];
    float4 x1 = *(const float4*)&g_XR[(size_t)node * HC + fb + 4];
    float xr[8] = {x0.x, x0.y, x0.z, x0.w, x1.x, x1.y, x1.z, x1.w};
    float4 a0 = *(const float4*)&att[fb];
    float4 a1 = *(const float4*)&att[fb + 4];
    float at[8] = {a0.x, a0.y, a0.z, a0.w, a1.x, a1.y, a1.z, a1.w};

    float acc[8];
    #pragma unroll
    for (int j = 0; j < 8; j++) acc[j] = 0.f;
    float m = -CUDART_INF_F, den = 0.f;

    int st = g_off[node];
    int en = st + g_deg[node];
    int e = st;

    // ---- 2-stage pipelined pair loop ----
    float4 c0a, c0b, c1a, c1b;
    bool have = (e + 1 < en);
    if (have) {
        int s0 = g_esrc[e], s1 = g_esrc[e + 1];
        const float4* p0 = (const float4*)&g_XL[(size_t)s0 * HC + fb];
        const float4* p1 = (const float4*)&g_XL[(size_t)s1 * HC + fb];
        c0a = p0[0]; c0b = p0[1];
        c1a = p1[0]; c1b = p1[1];
    }
    while (have) {
        int e2 = e + 2;
        bool nxt = (e2 + 1 < en);
        float4 n0a, n0b, n1a, n1b;
        if (nxt) {
            int s0 = g_esrc[e2], s1 = g_esrc[e2 + 1];
            const float4* p0 = (const float4*)&g_XL[(size_t)s0 * HC + fb];
            const float4* p1 = (const float4*)&g_XL[(size_t)s1 * HC + fb];
            n0a = p0[0]; n0b = p0[1];
            n1a = p1[0]; n1b = p1[1];
        }

        float v0[8] = {c0a.x, c0a.y, c0a.z, c0a.w, c0b.x, c0b.y, c0b.z, c0b.w};
        float v1[8] = {c1a.x, c1a.y, c1a.z, c1a.w, c1b.x, c1b.y, c1b.z, c1b.w};

        float p0s = 0.f, p1s = 0.f;
        #pragma unroll
        for (int j = 0; j < 8; j++) {
            float t0 = v0[j] + xr[j];
            float t1 = v1[j] + xr[j];
            t0 = (t0 > 0.f) ? t0 : 0.2f * t0;
            t1 = (t1 > 0.f) ? t1 : 0.2f * t1;
            p0s = fmaf(t0, at[j], p0s);
            p1s = fmaf(t1, at[j], p1s);
        }
        #pragma unroll
        for (int o = 1; o <= 4; o <<= 1) {
            p0s += __shfl_xor_sync(0xFFFFFFFFu, p0s, o);
            p1s += __shfl_xor_sync(0xFFFFFFFFu, p1s, o);
        }

        float mn = fmaxf(m, fmaxf(p0s, p1s));
        float sc = __expf(m - mn);
        float w0 = __expf(p0s - mn);
        float w1 = __expf(p1s - mn);
        den = fmaf(den, sc, w0 + w1);
        #pragma unroll
        for (int j = 0; j < 8; j++)
            acc[j] = fmaf(acc[j], sc, fmaf(w0, v0[j], w1 * v1[j]));
        m = mn;

        if (nxt) { c0a = n0a; c0b = n0b; c1a = n1a; c1b = n1b; }
        e = e2;
        have = nxt;
    }
    // remainder: single edge
    if (e < en) {
        int s = g_esrc[e];
        float4 u0 = *(const float4*)&g_XL[(size_t)s * HC + fb];
        float4 u1 = *(const float4*)&g_XL[(size_t)s * HC + fb + 4];
        float v[8] = {u0.x, u0.y, u0.z, u0.w, u1.x, u1.y, u1.z, u1.w};
        float ps = 0.f;
        #pragma unroll
        for (int j = 0; j < 8; j++) {
            float t = v[j] + xr[j];
            t = (t > 0.f) ? t : 0.2f * t;
            ps = fmaf(t, at[j], ps);
        }
        #pragma unroll
        for (int o = 1; o <= 4; o <<= 1)
            ps += __shfl_xor_sync(0xFFFFFFFFu, ps, o);
        float mn = fmaxf(m, ps);
        float sc = __expf(m - mn);
        float w = __expf(ps - mn);
        den = fmaf(den, sc, w);
        #pragma unroll
        for (int j = 0; j < 8; j++) acc[j] = fmaf(acc[j], sc, w * v[j]);
        m = mn;
    }

    float inv = 1.f / den;
    float4 bb0 = *(const float4*)&bias[fb];
    float4 bb1 = *(const float4*)&bias[fb + 4];
    float bs[8] = {bb0.x, bb0.y, bb0.z, bb0.w, bb1.x, bb1.y, bb1.z, bb1.w};
    float o[8];
    #pragma unroll
    for (int j = 0; j < 8; j++) o[j] = fmaf(acc[j], inv, bs[j]);

    if (PACK) {
        uint32_t hw[4], lw[4];
        #pragma unroll
        for (int i = 0; i < 4; i++) {
            float r0 = fmaxf(o[2 * i], 0.f);
            float r1 = fmaxf(o[2 * i + 1], 0.f);
            __nv_bfloat16 h0 = __float2bfloat16(r0);
            __nv_bfloat16 h1 = __float2bfloat16(r1);
            __nv_bfloat16 l0 = __float2bfloat16(r0 - __bfloat162float(h0));
            __nv_bfloat16 l1 = __float2bfloat16(r1 - __bfloat162float(h1));
            hw[i] = (uint32_t)__bfloat16_as_ushort(h0) |
                    ((uint32_t)__bfloat16_as_ushort(h1) << 16);
            lw[i] = (uint32_t)__bfloat16_as_ushort(l0) |
                    ((uint32_t)__bfloat16_as_ushort(l1) << 16);
        }
        size_t base = (size_t)node * 512 + fb;
        *(uint4*)&g_Ab[base]       = make_uint4(hw[0], hw[1], hw[2], hw[3]);
        *(uint4*)&g_Ab[base + 256] = make_uint4(lw[0], lw[1], lw[2], lw[3]);
    } else {
        *(float4*)&g_H[(size_t)node * HC + fb] =
            make_float4(o[0], o[1], o[2], o[3]);
        *(float4*)&g_H[(size_t)node * HC + fb + 4] =
            make_float4(o[4], o[5], o[6], o[7]);
    }
}

// ---------------- pooling ----------------
__global__ void k_pool(const int* __restrict__ batch) {
    int f = threadIdx.x;
    int n0 = blockIdx.x * 256;
    int n1 = min(n0 + 256, NN);
    int curg = -1;
    float s = 0.f, mx = -CUDART_INF_F;
    for (int n = n0; n < n1; n++) {
        int g = batch[n];
        float v = g_H[(size_t)n * HC + f];
        if (g != curg) {
            if (curg >= 0) {
                atomicAdd(&g_psum[curg * HC + f], s);
                atomicMax(&g_pmax[curg * HC + f], fkey(mx));
            }
            curg = g; s = 0.f; mx = -CUDART_INF_F;
        }
        s += v;
        mx = fmaxf(mx, v);
    }
    if (curg >= 0) {
        atomicAdd(&g_psum[curg * HC + f], s);
        atomicMax(&g_pmax[curg * HC + f], fkey(mx));
    }
}

// ---------------- classifier + softmax ----------------
__global__ void k_final(const float* __restrict__ Wout, const float* __restrict__ bout,
                        float* __restrict__ out) {
    int g = threadIdx.x;
    if (g >= NG) return;
    float c = (float)max(g_cnt[g], 1);
    float inv_c = 1.f / c;
    float l0 = bout[0], l1 = bout[1], l2 = bout[2];
    for (int f = 0; f < HC; f++) {
        float p = g_psum[g * HC + f] * inv_c + fdekey(g_pmax[g * HC + f]);
        l0 = fmaf(p, Wout[f * NCLS + 0], l0);
        l1 = fmaf(p, Wout[f * NCLS + 1], l1);
        l2 = fmaf(p, Wout[f * NCLS + 2], l2);
    }
    float mx = fmaxf(l0, fmaxf(l1, l2));
    float e0 = __expf(l0 - mx), e1 = __expf(l1 - mx), e2 = __expf(l2 - mx);
    float inv = 1.f / (e0 + e1 + e2);
    out[g * NCLS + 0] = e0 * inv;
    out[g * NCLS + 1] = e1 * inv;
    out[g * NCLS + 2] = e2 * inv;
}

// ---------------- launch ----------------
extern "C" void kernel_launch(void* const* d_in, const int* in_sizes, int n_in,
                              void* d_out, int out_size) {
    const float* x     = (const float*)d_in[0];
    const int*   ei    = (const int*)d_in[1];
    const int*   batch = (const int*)d_in[2];
    const float* Wl[3]   = {(const float*)d_in[3],  (const float*)d_in[9],  (const float*)d_in[15]};
    const float* bl[3]   = {(const float*)d_in[4],  (const float*)d_in[10], (const float*)d_in[16]};
    const float* Wr[3]   = {(const float*)d_in[5],  (const float*)d_in[11], (const float*)d_in[17]};
    const float* br[3]   = {(const float*)d_in[6],  (const float*)d_in[12], (const float*)d_in[18]};
    const float* att[3]  = {(const float*)d_in[7],  (const float*)d_in[13], (const float*)d_in[19]};
    const float* bias[3] = {(const float*)d_in[8],  (const float*)d_in[14], (const float*)d_in[20]};
    const float* Wout    = (const float*)d_in[21];
    const float* bout    = (const float*)d_in[22];
    float* out = (float*)d_out;

    (void)in_sizes; (void)n_in; (void)out_size;

    static bool attr_done = false;
    if (!attr_done) {
        cudaFuncSetAttribute((const void*)k_gemm<256, 128>,
                             cudaFuncAttributeMaxDynamicSharedMemorySize, GEMM_SMEM);
        cudaFuncSetAttribute((const void*)k_gemm<512, 256>,
                             cudaFuncAttributeMaxDynamicSharedMemorySize, GEMM_SMEM);
        attr_done = true;
    }

    dim3 ggrid((NN + 127) / 128, 4);
    int abl = (NN * 32 + 255) / 256;
    int ebl = (EP + 255) / 256;
    int sblocks = (NN + 1023) / 1024;   // 49

    // 1: fused convA | convW | init
    k_prep<<<PB_I, 256>>>(x, Wl[0], Wr[0], Wl[1], Wr[1], Wl[2], Wr[2]);
    // 2: deg histogram + graph counts (after init)
    k_deg<<<ebl, 256>>>(ei, batch);
    // 3: block-local scan
    k_scan1<<<sblocks, 1024>>>();
    // 4: layer-0 GEMM  <-- ncu capture slot (sentinel)
    k_gemm<256, 128><<<ggrid, 256, GEMM_SMEM>>>(0, bl[0], br[0]);
    // 5-6: finish scan
    k_scan2<<<1, 64>>>(sblocks);
    k_scan3<<<(NN + 255) / 256, 256>>>();
    // 7: scatter
    k_scatter<<<ebl, 256>>>(ei);
    // 8: layer-0 aggregation (packs relu(h) -> g_Ab)
    k_agg<true><<<abl, 256>>>(att[0], bias[0]);
    // 9-10: layer 1
    k_gemm<512, 256><<<ggrid, 256, GEMM_SMEM>>>(1, bl[1], br[1]);
    k_agg<true><<<abl, 256>>>(att[1], bias[1]);
    // 11-12: layer 2
    k_gemm<512, 256><<<ggrid, 256, GEMM_SMEM>>>(2, bl[2], br[2]);
    k_agg<false><<<abl, 256>>>(att[2], bias[2]);
    // 13-14: pooling + classifier
    k_pool<<<(NN + 255) / 256, 256>>>(batch);
    k_final<<<1, 64>>>(Wout, bout, out);
}

// round 14
// speedup vs baseline: 1.0770x; 1.0770x over previous
#include <cuda_runtime.h>
#include <cuda_bf16.h>
#include <math_constants.h>
#include <cstdint>

// Problem constants (fixed by the dataset)
#define NN   50000
#define EE   600000
#define EP   (EE + NN)     // edges + self loops = 650000
#define FIN  128
#define HC   256           // H*C = 4*64
#define NG   64            // graphs
#define NCLS 3

#define SMEM_SWIZZLE_128B(b) ((b) ^ (((b) >> 3) & 0x70))

__device__ __forceinline__ uint32_t smem_to_u32(const void* p) {
    uint32_t a;
    asm("{ .reg .u64 t; cvta.to.shared.u64 t, %1; cvt.u32.u64 %0, t; }" : "=r"(a) : "l"(p));
    return a;
}
__device__ __forceinline__ void cp_async16(uint32_t dst, const void* src, bool pred) {
    int sz = pred ? 16 : 0;
    asm volatile("cp.async.cg.shared.global [%0], [%1], 16, %2;"
                 :: "r"(dst), "l"(src), "r"(sz) : "memory");
}
template <int N>
__device__ __forceinline__ void cp_async_wait() {
    asm volatile("cp.async.wait_group %0;" :: "n"(N) : "memory");
}
__device__ __forceinline__ void ldsm_x4(uint32_t* r, uint32_t addr) {
    asm volatile("ldmatrix.sync.aligned.m8n8.x4.shared.b16 {%0,%1,%2,%3}, [%4];"
                 : "=r"(r[0]), "=r"(r[1]), "=r"(r[2]), "=r"(r[3]) : "r"(addr));
}
__device__ __forceinline__ void mma16816(float* c, const uint32_t* a, const uint32_t* b) {
    asm volatile("mma.sync.aligned.m16n8k16.row.col.f32.bf16.bf16.f32 "
                 "{%0,%1,%2,%3}, {%4,%5,%6,%7}, {%8,%9}, {%0,%1,%2,%3};"
                 : "+f"(c[0]), "+f"(c[1]), "+f"(c[2]), "+f"(c[3])
                 : "r"(a[0]), "r"(a[1]), "r"(a[2]), "r"(a[3]), "r"(b[0]), "r"(b[1]));
}

// ---------------- device scratch (no allocation allowed) ----------------
__device__ float g_XL[(size_t)NN * HC];
__device__ float g_XR[(size_t)NN * HC];
__device__ float g_H [(size_t)NN * HC];
__device__ __align__(16) __nv_bfloat16 g_Ab[(size_t)NN * 512];  // A [hi|lo], stride 2K
__device__ __align__(16) __nv_bfloat16 g_Wb0[512 * 128];        // layer0 B = Whi only, [n][K]
__device__ __align__(16) __nv_bfloat16 g_Wb1[512 * 256];        // layer1 B = Whi only
__device__ __align__(16) __nv_bfloat16 g_Wb2[512 * 256];        // layer2 B = Whi only
__device__ int   g_deg[NN];
__device__ int   g_off[NN];
__device__ int   g_cur[NN];
__device__ int   g_esrc[EP];
__device__ int   g_bsum[64];
__device__ int   g_bsumex[64];
__device__ float    g_psum[NG * HC];
__device__ unsigned g_pmax[NG * HC];
__device__ int      g_cnt[NG];

__device__ __forceinline__ unsigned fkey(float f) {
    unsigned b = __float_as_uint(f);
    return (b & 0x80000000u) ? ~b : (b | 0x80000000u);
}
__device__ __forceinline__ float fdekey(unsigned u) {
    return (u & 0x80000000u) ? __uint_as_float(u & 0x7FFFFFFFu) : __uint_as_float(~u);
}

// ---------------- fused prologue: convA | convW | init ----------------
#define PB_A 6250                    // convA: NN*FIN/4 / 256
#define PB_W (PB_A + 1536)           // convW: 6 matrices x 256 blocks
#define PB_I (PB_W + 256)            // init
__global__ void k_prep(const float* __restrict__ x,
                       const float* __restrict__ Wl0, const float* __restrict__ Wr0,
                       const float* __restrict__ Wl1, const float* __restrict__ Wr1,
                       const float* __restrict__ Wl2, const float* __restrict__ Wr2) {
    int b = blockIdx.x, tid = threadIdx.x;
    if (b < PB_A) {
        // convA: fp32 -> bf16 [hi|lo], stride 256
        int i = b * 256 + tid;
        if (i >= NN * FIN / 4) return;
        int row = i >> 5, j = (i & 31) * 4;
        float4 v = ((const float4*)x)[i];
        __nv_bfloat16 hx = __float2bfloat16(v.x), hy = __float2bfloat16(v.y);
        __nv_bfloat16 hz = __float2bfloat16(v.z), hw = __float2bfloat16(v.w);
        __nv_bfloat162 h01(hx, hy), h23(hz, hw);
        __nv_bfloat162 l01(__float2bfloat16(v.x - __bfloat162float(hx)),
                           __float2bfloat16(v.y - __bfloat162float(hy)));
        __nv_bfloat162 l23(__float2bfloat16(v.z - __bfloat162float(hz)),
                           __float2bfloat16(v.w - __bfloat162float(hw)));
        size_t base = (size_t)row * 256;
        *(__nv_bfloat162*)&g_Ab[base + j]           = h01;
        *(__nv_bfloat162*)&g_Ab[base + j + 2]       = h23;
        *(__nv_bfloat162*)&g_Ab[base + 128 + j]     = l01;
        *(__nv_bfloat162*)&g_Ab[base + 128 + j + 2] = l23;
    } else if (b < PB_W) {
        // convW: W [K][256] fp32 -> dst[n][K] bf16 (hi)
        int bb = b - PB_A;
        int y = bb >> 8;
        int K = (y < 2) ? FIN : HC;
        int i = (bb & 255) * 256 + tid;
        if (i >= K * 256) return;
        const float* W;
        __nv_bfloat16* dst;
        switch (y) {
            case 0: W = Wl0; dst = g_Wb0; break;
            case 1: W = Wr0; dst = g_Wb0; break;
            case 2: W = Wl1; dst = g_Wb1; break;
            case 3: W = Wr1; dst = g_Wb1; break;
            case 4: W = Wl2; dst = g_Wb2; break;
            default: W = Wr2; dst = g_Wb2; break;
        }
        int nbase = (y & 1) * 256;
        int k = i >> 8, n = i & 255;
        dst[(size_t)(nbase + n) * K + k] = __float2bfloat16(W[i]);
    } else {
        // init: deg/psum/pmax/cnt
        int i = (b - PB_W) * 256 + tid;
        int stride = 256 * 256;
        for (int j = i; j < NN; j += stride) g_deg[j] = 0;
        for (int j = i; j < NG * HC; j += stride) { g_psum[j] = 0.f; g_pmax[j] = 0x007FFFFFu; }
        for (int j = i; j < NG; j += stride) g_cnt[j] = 0;
    }
}

// deg histogram + graph counts (after k_prep's init has completed)
__global__ void k_deg(const int* __restrict__ ei, const int* __restrict__ batch) {
    int i = blockIdx.x * blockDim.x + threadIdx.x;
    if (i < NN) atomicAdd(&g_cnt[batch[i]], 1);
    if (i >= EP) return;
    int d = (i < EE) ? ei[EE + i] : (i - EE);
    atomicAdd(&g_deg[d], 1);
}

// ---------------- 3-phase scan ----------------
__global__ void k_scan1() {
    __shared__ int wsum[32];
    int b = blockIdx.x, tid = threadIdx.x, lane = tid & 31, wid = tid >> 5;
    int i = b * 1024 + tid;
    int v = (i < NN) ? g_deg[i] : 0;
    int x = v;
    #pragma unroll
    for (int o = 1; o < 32; o <<= 1) {
        int t = __shfl_up_sync(0xFFFFFFFFu, x, o);
        if (lane >= o) x += t;
    }
    if (lane == 31) wsum[wid] = x;
    __syncthreads();
    if (wid == 0) {
        int orig = wsum[lane];
        int y = orig;
        #pragma unroll
        for (int o = 1; o < 32; o <<= 1) {
            int t = __shfl_up_sync(0xFFFFFFFFu, y, o);
            if (lane >= o) y += t;
        }
        wsum[lane] = y - orig;
    }
    __syncthreads();
    int incl = x + wsum[wid];
    if (i < NN) g_off[i] = incl - v;
    if (tid == 1023) g_bsum[b] = incl;
}

__global__ void k_scan2(int nblocks) {
    __shared__ int s[64];
    int tid = threadIdx.x;
    s[tid] = (tid < nblocks) ? g_bsum[tid] : 0;
    __syncthreads();
    #pragma unroll
    for (int o = 1; o < 64; o <<= 1) {
        int t = (tid >= o) ? s[tid - o] : 0;
        __syncthreads();
        s[tid] += t;
        __syncthreads();
    }
    if (tid < nblocks) g_bsumex[tid] = s[tid] - g_bsum[tid];
}

__global__ void k_scan3() {
    int i = blockIdx.x * blockDim.x + threadIdx.x;
    if (i >= NN) return;
    int off = g_off[i] + g_bsumex[i >> 10];
    g_off[i] = off;
    g_cur[i] = off;
}

__global__ void k_scatter(const int* __restrict__ ei) {
    int i = blockIdx.x * blockDim.x + threadIdx.x;
    if (i >= EP) return;
    int s, d;
    if (i < EE) { s = ei[i]; d = ei[EE + i]; }
    else        { s = d = i - EE; }
    int pos = atomicAdd(&g_cur[d], 1);
    g_esrc[pos] = s;
}

// ---------------- mma.sync bf16 GEMM ----------------
// CTA tile 128 x 128, 256 threads = 8 warps (4M x 2N), warp tile 32x64.
// 3-stage cp.async pipeline, K-chunk 64. 2 CTAs/SM.
// 2-term split: D = Ahi*Bhi + Alo*Bhi. Logical K = KLOG = 2K.
#define A_BYTES (128 * 64 * 2)   // 16KB
#define B_BYTES (128 * 64 * 2)   // 16KB
#define GEMM_SMEM (3 * (A_BYTES + B_BYTES))   // 96KB

template <int KLOG, int KB>
__global__ void __launch_bounds__(256, 2) k_gemm(int wsel,
                                                 const float* __restrict__ biasL,
                                                 const float* __restrict__ biasR) {
    extern __shared__ char smem[];
    const __nv_bfloat16* Wb = (wsel == 0) ? g_Wb0 : (wsel == 1) ? g_Wb1 : g_Wb2;
    const int tid = threadIdx.x;
    const int lane = tid & 31, wid = tid >> 5;
    const int m0 = blockIdx.x * 128;
    const int n0 = blockIdx.y * 128;
    const int wm = (wid & 3) * 32;
    const int wn = (wid >> 2) * 64;

    uint32_t sbase = smem_to_u32(smem);

    float acc[2][8][4];
    #pragma unroll
    for (int mt = 0; mt < 2; mt++)
        #pragma unroll
        for (int nt = 0; nt < 8; nt++)
            #pragma unroll
            for (int q = 0; q < 4; q++) acc[mt][nt][q] = 0.f;

    constexpr int NT = KLOG / 64;

    auto issue = [&](int slot, int c) {
        uint32_t ab = sbase + slot * A_BYTES;
        uint32_t bb = sbase + 3 * A_BYTES + slot * B_BYTES;
        int ka = c * 64;
        int kb = (c * 64) & (KB - 1);
        #pragma unroll
        for (int i = 0; i < 4; i++) {
            int chunk = tid + i * 256;
            int row = chunk >> 3, seg = chunk & 7;
            int sw = SMEM_SWIZZLE_128B(row * 128 + seg * 16);
            bool ok = (m0 + row) < NN;
            int grow = ok ? (m0 + row) : 0;
            cp_async16(ab + sw, &g_Ab[(size_t)grow * KLOG + ka + seg * 8], ok);
        }
        #pragma unroll
        for (int i = 0; i < 4; i++) {
            int chunk = tid + i * 256;
            int row = chunk >> 3, seg = chunk & 7;
            int sw = SMEM_SWIZZLE_128B(row * 128 + seg * 16);
            cp_async16(bb + sw, &Wb[(size_t)(n0 + row) * KB + kb + seg * 8], true);
        }
        asm volatile("cp.async.commit_group;" ::: "memory");
    };

    issue(0, 0);
    issue(1, 1);

    for (int t = 0; t < NT; t++) {
        if (t + 1 < NT) cp_async_wait<1>(); else cp_async_wait<0>();
        __syncthreads();
        if (t + 2 < NT) issue((t + 2) % 3, t + 2);

        int slot = t % 3;
        uint32_t ab = sbase + slot * A_BYTES;
        uint32_t bb = sbase + 3 * A_BYTES + slot * B_BYTES;
        #pragma unroll
        for (int ks = 0; ks < 4; ks++) {
            int k16 = ks * 16;
            uint32_t a[2][4];
            #pragma unroll
            for (int mt = 0; mt < 2; mt++) {
                int row = wm + mt * 16 + (lane & 15);
                int col = k16 + (lane >> 4) * 8;
                ldsm_x4(a[mt], ab + SMEM_SWIZZLE_128B(row * 128 + col * 2));
            }
            uint32_t b[4][4];
            #pragma unroll
            for (int nt = 0; nt < 4; nt++) {
                int row = wn + nt * 16 + (lane & 7) + ((lane >> 4) << 3);
                int col = k16 + ((lane >> 3) & 1) * 8;
                ldsm_x4(b[nt], bb + SMEM_SWIZZLE_128B(row * 128 + col * 2));
            }
            #pragma unroll
            for (int mt = 0; mt < 2; mt++)
                #pragma unroll
                for (int nt = 0; nt < 8; nt++)
                    mma16816(acc[mt][nt], a[mt], &b[nt >> 1][(nt & 1) * 2]);
        }
    }

    // epilogue: bias add + split XL/XR
    bool halfR = (n0 + wn) >= 256;
    float* outp = halfR ? g_XR : g_XL;
    const float* bias = halfR ? biasR : biasL;
    int cb = n0 + wn - (halfR ? 256 : 0);
    #pragma unroll
    for (int mt = 0; mt < 2; mt++) {
        int r0 = m0 + wm + mt * 16 + (lane >> 2);
        #pragma unroll
        for (int nt = 0; nt < 8; nt++) {
            int c = cb + nt * 8 + (lane & 3) * 2;
            float b0 = bias[c], b1 = bias[c + 1];
            if (r0 < NN)
                *(float2*)&outp[(size_t)r0 * HC + c] =
                    make_float2(acc[mt][nt][0] + b0, acc[mt][nt][1] + b1);
            if (r0 + 8 < NN)
                *(float2*)&outp[(size_t)(r0 + 8) * HC + c] =
                    make_float2(acc[mt][nt][2] + b0, acc[mt][nt][3] + b1);
        }
    }
}

// ---------------- warp-per-node edge softmax + aggregation (round-8/12 form) ----------------
// PACK=true: write relu(h) as bf16 [hi|lo] (stride 512) directly to g_Ab.
// PACK=false: write h (fp32) to g_H (feeds pooling).
template <bool PACK>
__global__ void k_agg(const float* __restrict__ att, const float* __restrict__ bias) {
    int gt = blockIdx.x * blockDim.x + threadIdx.x;
    int node = gt >> 5;
    int lane = gt & 31;
    if (node >= NN) return;

    int fb = lane * 8;

    float4 x0 = *(const float4*)&g_XR[(size_t)node * HC + fb];
    float4 x1 = *(const float4*)&g_XR[(size_t)node * HC + fb + 4];
    float xr[8] = {x0.x, x0.y, x0.z, x0.w, x1.x, x1.y, x1.z, x1.w};
    float4 a0 = *(const float4*)&att[fb];
    float4 a1 = *(const float4*)&att[fb + 4];
    float at[8] = {a0.x, a0.y, a0.z, a0.w, a1.x, a1.y, a1.z, a1.w};

    float acc[8];
    #pragma unroll
    for (int j = 0; j < 8; j++) acc[j] = 0.f;
    float m = -CUDART_INF_F, den = 0.f;

    int st = g_off[node];
    int en = st + g_deg[node];

    int e = st;
    for (; e + 1 < en; e += 2) {
        int s0 = g_esrc[e];
        int s1 = g_esrc[e + 1];
        float4 u0 = *(const float4*)&g_XL[(size_t)s0 * HC + fb];
        float4 u1 = *(const float4*)&g_XL[(size_t)s0 * HC + fb + 4];
        float4 w0v = *(const float4*)&g_XL[(size_t)s1 * HC + fb];
        float4 w1v = *(const float4*)&g_XL[(size_t)s1 * HC + fb + 4];
        float v0[8] = {u0.x, u0.y, u0.z, u0.w, u1.x, u1.y, u1.z, u1.w};
        float v1[8] = {w0v.x, w0v.y, w0v.z, w0v.w, w1v.x, w1v.y, w1v.z, w1v.w};

        float p0 = 0.f, p1 = 0.f;
        #pragma unroll
        for (int j = 0; j < 8; j++) {
            float t0 = v0[j] + xr[j];
            float t1 = v1[j] + xr[j];
            t0 = (t0 > 0.f) ? t0 : 0.2f * t0;
            t1 = (t1 > 0.f) ? t1 : 0.2f * t1;
            p0 = fmaf(t0, at[j], p0);
            p1 = fmaf(t1, at[j], p1);
        }
        #pragma unroll
        for (int o = 1; o <= 4; o <<= 1) {
            p0 += __shfl_xor_sync(0xFFFFFFFFu, p0, o);
            p1 += __shfl_xor_sync(0xFFFFFFFFu, p1, o);
        }

        float mn = fmaxf(m, fmaxf(p0, p1));
        float sc = __expf(m - mn);
        float w0 = __expf(p0 - mn);
        float w1 = __expf(p1 - mn);
        den = fmaf(den, sc, w0 + w1);
        #pragma unroll
        for (int j = 0; j < 8; j++)
            acc[j] = fmaf(acc[j], sc, fmaf(w0, v0[j], w1 * v1[j]));
        m = mn;
    }
    if (e < en) {
        int s = g_esrc[e];
        float4 u0 = *(const float4*)&g_XL[(size_t)s * HC + fb];
        float4 u1 = *(const float4*)&g_XL[(size_t)s * HC + fb + 4];
        float v[8] = {u0.x, u0.y, u0.z, u0.w, u1.x, u1.y, u1.z, u1.w};
        float ps = 0.f;
        #pragma unroll
        for (int j = 0; j < 8; j++) {
            float t = v[j] + xr[j];
            t = (t > 0.f) ? t : 0.2f * t;
            ps = fmaf(t, at[j], ps);
        }
        #pragma unroll
        for (int o = 1; o <= 4; o <<= 1)
            ps += __shfl_xor_sync(0xFFFFFFFFu, ps, o);
        float mn = fmaxf(m, ps);
        float sc = __expf(m - mn);
        float w = __expf(ps - mn);
        den = fmaf(den, sc, w);
        #pragma unroll
        for (int j = 0; j < 8; j++) acc[j] = fmaf(acc[j], sc, w * v[j]);
        m = mn;
    }

    float inv = 1.f / den;
    float4 bb0 = *(const float4*)&bias[fb];
    float4 bb1 = *(const float4*)&bias[fb + 4];
    float bs[8] = {bb0.x, bb0.y, bb0.z, bb0.w, bb1.x, bb1.y, bb1.z, bb1.w};
    float o[8];
    #pragma unroll
    for (int j = 0; j < 8; j++) o[j] = fmaf(acc[j], inv, bs[j]);

    if (PACK) {
        uint32_t hw[4], lw[4];
        #pragma unroll
        for (int i = 0; i < 4; i++) {
            float r0 = fmaxf(o[2 * i], 0.f);
            float r1 = fmaxf(o[2 * i + 1], 0.f);
            __nv_bfloat16 h0 = __float2bfloat16(r0);
            __nv_bfloat16 h1 = __float2bfloat16(r1);
            __nv_bfloat16 l0 = __float2bfloat16(r0 - __bfloat162float(h0));
            __nv_bfloat16 l1 = __float2bfloat16(r1 - __bfloat162float(h1));
            hw[i] = (uint32_t)__bfloat16_as_ushort(h0) |
                    ((uint32_t)__bfloat16_as_ushort(h1) << 16);
            lw[i] = (uint32_t)__bfloat16_as_ushort(l0) |
                    ((uint32_t)__bfloat16_as_ushort(l1) << 16);
        }
        size_t base = (size_t)node * 512 + fb;
        *(uint4*)&g_Ab[base]       = make_uint4(hw[0], hw[1], hw[2], hw[3]);
        *(uint4*)&g_Ab[base + 256] = make_uint4(lw[0], lw[1], lw[2], lw[3]);
    } else {
        *(float4*)&g_H[(size_t)node * HC + fb] =
            make_float4(o[0], o[1], o[2], o[3]);
        *(float4*)&g_H[(size_t)node * HC + fb + 4] =
            make_float4(o[4], o[5], o[6], o[7]);
    }
}

// ---------------- pooling ----------------
__global__ void k_pool(const int* __restrict__ batch) {
    int f = threadIdx.x;
    int n0 = blockIdx.x * 256;
    int n1 = min(n0 + 256, NN);
    int curg = -1;
    float s = 0.f, mx = -CUDART_INF_F;
    for (int n = n0; n < n1; n++) {
        int g = batch[n];
        float v = g_H[(size_t)n * HC + f];
        if (g != curg) {
            if (curg >= 0) {
                atomicAdd(&g_psum[curg * HC + f], s);
                atomicMax(&g_pmax[curg * HC + f], fkey(mx));
            }
            curg = g; s = 0.f; mx = -CUDART_INF_F;
        }
        s += v;
        mx = fmaxf(mx, v);
    }
    if (curg >= 0) {
        atomicAdd(&g_psum[curg * HC + f], s);
        atomicMax(&g_pmax[curg * HC + f], fkey(mx));
    }
}

// ---------------- classifier + softmax ----------------
__global__ void k_final(const float* __restrict__ Wout, const float* __restrict__ bout,
                        float* __restrict__ out) {
    int g = threadIdx.x;
    if (g >= NG) return;
    float c = (float)max(g_cnt[g], 1);
    float inv_c = 1.f / c;
    float l0 = bout[0], l1 = bout[1], l2 = bout[2];
    for (int f = 0; f < HC; f++) {
        float p = g_psum[g * HC + f] * inv_c + fdekey(g_pmax[g * HC + f]);
        l0 = fmaf(p, Wout[f * NCLS + 0], l0);
        l1 = fmaf(p, Wout[f * NCLS + 1], l1);
        l2 = fmaf(p, Wout[f * NCLS + 2], l2);
    }
    float mx = fmaxf(l0, fmaxf(l1, l2));
    float e0 = __expf(l0 - mx), e1 = __expf(l1 - mx), e2 = __expf(l2 - mx);
    float inv = 1.f / (e0 + e1 + e2);
    out[g * NCLS + 0] = e0 * inv;
    out[g * NCLS + 1] = e1 * inv;
    out[g * NCLS + 2] = e2 * inv;
}

// ---------------- launch ----------------
extern "C" void kernel_launch(void* const* d_in, const int* in_sizes, int n_in,
                              void* d_out, int out_size) {
    const float* x     = (const float*)d_in[0];
    const int*   ei    = (const int*)d_in[1];
    const int*   batch = (const int*)d_in[2];
    const float* Wl[3]   = {(const float*)d_in[3],  (const float*)d_in[9],  (const float*)d_in[15]};
    const float* bl[3]   = {(const float*)d_in[4],  (const float*)d_in[10], (const float*)d_in[16]};
    const float* Wr[3]   = {(const float*)d_in[5],  (const float*)d_in[11], (const float*)d_in[17]};
    const float* br[3]   = {(const float*)d_in[6],  (const float*)d_in[12], (const float*)d_in[18]};
    const float* att[3]  = {(const float*)d_in[7],  (const float*)d_in[13], (const float*)d_in[19]};
    const float* bias[3] = {(const float*)d_in[8],  (const float*)d_in[14], (const float*)d_in[20]};
    const float* Wout    = (const float*)d_in[21];
    const float* bout    = (const float*)d_in[22];
    float* out = (float*)d_out;

    (void)in_sizes; (void)n_in; (void)out_size;

    static bool attr_done = false;
    if (!attr_done) {
        cudaFuncSetAttribute((const void*)k_gemm<256, 128>,
                             cudaFuncAttributeMaxDynamicSharedMemorySize, GEMM_SMEM);
        cudaFuncSetAttribute((const void*)k_gemm<512, 256>,
                             cudaFuncAttributeMaxDynamicSharedMemorySize, GEMM_SMEM);
        attr_done = true;
    }

    dim3 ggrid((NN + 127) / 128, 4);
    int abl = (NN * 32 + 127) / 128;    // k_agg: 128 threads/block -> finer scheduling
    int ebl = (EP + 255) / 256;
    int sblocks = (NN + 1023) / 1024;   // 49

    // 1: fused convA | convW | init
    k_prep<<<PB_I, 256>>>(x, Wl[0], Wr[0], Wl[1], Wr[1], Wl[2], Wr[2]);
    // 2: deg histogram + graph counts (after init)
    k_deg<<<ebl, 256>>>(ei, batch);
    // 3: block-local scan
    k_scan1<<<sblocks, 1024>>>();
    // 4: layer-0 GEMM  <-- ncu capture slot (sentinel)
    k_gemm<256, 128><<<ggrid, 256, GEMM_SMEM>>>(0, bl[0], br[0]);
    // 5-6: finish scan
    k_scan2<<<1, 64>>>(sblocks);
    k_scan3<<<(NN + 255) / 256, 256>>>();
    // 7: scatter
    k_scatter<<<ebl, 256>>>(ei);
    // 8: layer-0 aggregation (packs relu(h) -> g_Ab)
    k_agg<true><<<abl, 128>>>(att[0], bias[0]);
    // 9-10: layer 1
    k_gemm<512, 256><<<ggrid, 256, GEMM_SMEM>>>(1, bl[1], br[1]);
    k_agg<true><<<abl, 128>>>(att[1], bias[1]);
    // 11-12: layer 2
    k_gemm<512, 256><<<ggrid, 256, GEMM_SMEM>>>(2, bl[2], br[2]);
    k_agg<false><<<abl, 128>>>(att[2], bias[2]);
    // 13-14: pooling + classifier
    k_pool<<<(NN + 255) / 256, 256>>>(batch);
    k_final<<<1, 64>>>(Wout, bout, out);
}

// round 15
// speedup vs baseline: 1.0901x; 1.0122x over previous
#include <cuda_runtime.h>
#include <cuda_bf16.h>
#include <math_constants.h>
#include <cstdint>

// Problem constants (fixed by the dataset)
#define NN   50000
#define EE   600000
#define EP   (EE + NN)     // edges + self loops = 650000
#define FIN  128
#define HC   256           // H*C = 4*64
#define NG   64            // graphs
#define NCLS 3

#define SMEM_SWIZZLE_128B(b) ((b) ^ (((b) >> 3) & 0x70))

__device__ __forceinline__ uint32_t smem_to_u32(const void* p) {
    uint32_t a;
    asm("{ .reg .u64 t; cvta.to.shared.u64 t, %1; cvt.u32.u64 %0, t; }" : "=r"(a) : "l"(p));
    return a;
}
__device__ __forceinline__ void cp_async16(uint32_t dst, const void* src, bool pred) {
    int sz = pred ? 16 : 0;
    asm volatile("cp.async.cg.shared.global [%0], [%1], 16, %2;"
                 :: "r"(dst), "l"(src), "r"(sz) : "memory");
}
template <int N>
__device__ __forceinline__ void cp_async_wait() {
    asm volatile("cp.async.wait_group %0;" :: "n"(N) : "memory");
}
__device__ __forceinline__ void ldsm_x4(uint32_t* r, uint32_t addr) {
    asm volatile("ldmatrix.sync.aligned.m8n8.x4.shared.b16 {%0,%1,%2,%3}, [%4];"
                 : "=r"(r[0]), "=r"(r[1]), "=r"(r[2]), "=r"(r[3]) : "r"(addr));
}
__device__ __forceinline__ void mma16816(float* c, const uint32_t* a, const uint32_t* b) {
    asm volatile("mma.sync.aligned.m16n8k16.row.col.f32.bf16.bf16.f32 "
                 "{%0,%1,%2,%3}, {%4,%5,%6,%7}, {%8,%9}, {%0,%1,%2,%3};"
                 : "+f"(c[0]), "+f"(c[1]), "+f"(c[2]), "+f"(c[3])
                 : "r"(a[0]), "r"(a[1]), "r"(a[2]), "r"(a[3]), "r"(b[0]), "r"(b[1]));
}

// ---------------- device scratch (no allocation allowed) ----------------
__device__ float g_XL[(size_t)NN * HC];
__device__ float g_XR[(size_t)NN * HC];
__device__ float g_H [(size_t)NN * HC];
__device__ __align__(16) __nv_bfloat16 g_Ab[(size_t)NN * 512];  // A [hi|lo], stride 2K
__device__ __align__(16) __nv_bfloat16 g_Wb0[512 * 128];        // layer0 B = Whi only, [n][K]
__device__ __align__(16) __nv_bfloat16 g_Wb1[512 * 256];        // layer1 B = Whi only
__device__ __align__(16) __nv_bfloat16 g_Wb2[512 * 256];        // layer2 B = Whi only
__device__ int   g_deg[NN];
__device__ int   g_off[NN];
__device__ int   g_cur[NN];
__device__ int   g_esrc[EP];
__device__ int   g_bsum[64];
__device__ int   g_bsumex[64];
__device__ float    g_psum[NG * HC];
__device__ unsigned g_pmax[NG * HC];
__device__ int      g_cnt[NG];

__device__ __forceinline__ unsigned fkey(float f) {
    unsigned b = __float_as_uint(f);
    return (b & 0x80000000u) ? ~b : (b | 0x80000000u);
}
__device__ __forceinline__ float fdekey(unsigned u) {
    return (u & 0x80000000u) ? __uint_as_float(u & 0x7FFFFFFFu) : __uint_as_float(~u);
}

// ---------------- fused prologue: convA | convW | init ----------------
#define PB_A 6250                    // convA: NN*FIN/4 / 256
#define PB_W (PB_A + 1536)           // convW: 6 matrices x 256 blocks
#define PB_I (PB_W + 256)            // init
__global__ void k_prep(const float* __restrict__ x,
                       const float* __restrict__ Wl0, const float* __restrict__ Wr0,
                       const float* __restrict__ Wl1, const float* __restrict__ Wr1,
                       const float* __restrict__ Wl2, const float* __restrict__ Wr2) {
    int b = blockIdx.x, tid = threadIdx.x;
    if (b < PB_A) {
        // convA: fp32 -> bf16 [hi|lo], stride 256
        int i = b * 256 + tid;
        if (i >= NN * FIN / 4) return;
        int row = i >> 5, j = (i & 31) * 4;
        float4 v = ((const float4*)x)[i];
        __nv_bfloat16 hx = __float2bfloat16(v.x), hy = __float2bfloat16(v.y);
        __nv_bfloat16 hz = __float2bfloat16(v.z), hw = __float2bfloat16(v.w);
        __nv_bfloat162 h01(hx, hy), h23(hz, hw);
        __nv_bfloat162 l01(__float2bfloat16(v.x - __bfloat162float(hx)),
                           __float2bfloat16(v.y - __bfloat162float(hy)));
        __nv_bfloat162 l23(__float2bfloat16(v.z - __bfloat162float(hz)),
                           __float2bfloat16(v.w - __bfloat162float(hw)));
        size_t base = (size_t)row * 256;
        *(__nv_bfloat162*)&g_Ab[base + j]           = h01;
        *(__nv_bfloat162*)&g_Ab[base + j + 2]       = h23;
        *(__nv_bfloat162*)&g_Ab[base + 128 + j]     = l01;
        *(__nv_bfloat162*)&g_Ab[base + 128 + j + 2] = l23;
    } else if (b < PB_W) {
        // convW: W [K][256] fp32 -> dst[n][K] bf16 (hi)
        int bb = b - PB_A;
        int y = bb >> 8;
        int K = (y < 2) ? FIN : HC;
        int i = (bb & 255) * 256 + tid;
        if (i >= K * 256) return;
        const float* W;
        __nv_bfloat16* dst;
        switch (y) {
            case 0: W = Wl0; dst = g_Wb0; break;
            case 1: W = Wr0; dst = g_Wb0; break;
            case 2: W = Wl1; dst = g_Wb1; break;
            case 3: W = Wr1; dst = g_Wb1; break;
            case 4: W = Wl2; dst = g_Wb2; break;
            default: W = Wr2; dst = g_Wb2; break;
        }
        int nbase = (y & 1) * 256;
        int k = i >> 8, n = i & 255;
        dst[(size_t)(nbase + n) * K + k] = __float2bfloat16(W[i]);
    } else {
        // init: deg/psum/pmax/cnt
        int i = (b - PB_W) * 256 + tid;
        int stride = 256 * 256;
        for (int j = i; j < NN; j += stride) g_deg[j] = 0;
        for (int j = i; j < NG * HC; j += stride) { g_psum[j] = 0.f; g_pmax[j] = 0x007FFFFFu; }
        for (int j = i; j < NG; j += stride) g_cnt[j] = 0;
    }
}

// deg histogram + graph counts (after k_prep's init has completed)
__global__ void k_deg(const int* __restrict__ ei, const int* __restrict__ batch) {
    int i = blockIdx.x * blockDim.x + threadIdx.x;
    if (i < NN) atomicAdd(&g_cnt[batch[i]], 1);
    if (i >= EP) return;
    int d = (i < EE) ? ei[EE + i] : (i - EE);
    atomicAdd(&g_deg[d], 1);
}

// ---------------- 3-phase scan ----------------
__global__ void k_scan1() {
    __shared__ int wsum[32];
    int b = blockIdx.x, tid = threadIdx.x, lane = tid & 31, wid = tid >> 5;
    int i = b * 1024 + tid;
    int v = (i < NN) ? g_deg[i] : 0;
    int x = v;
    #pragma unroll
    for (int o = 1; o < 32; o <<= 1) {
        int t = __shfl_up_sync(0xFFFFFFFFu, x, o);
        if (lane >= o) x += t;
    }
    if (lane == 31) wsum[wid] = x;
    __syncthreads();
    if (wid == 0) {
        int orig = wsum[lane];
        int y = orig;
        #pragma unroll
        for (int o = 1; o < 32; o <<= 1) {
            int t = __shfl_up_sync(0xFFFFFFFFu, y, o);
            if (lane >= o) y += t;
        }
        wsum[lane] = y - orig;
    }
    __syncthreads();
    int incl = x + wsum[wid];
    if (i < NN) g_off[i] = incl - v;
    if (tid == 1023) g_bsum[b] = incl;
}

__global__ void k_scan2(int nblocks) {
    __shared__ int s[64];
    int tid = threadIdx.x;
    s[tid] = (tid < nblocks) ? g_bsum[tid] : 0;
    __syncthreads();
    #pragma unroll
    for (int o = 1; o < 64; o <<= 1) {
        int t = (tid >= o) ? s[tid - o] : 0;
        __syncthreads();
        s[tid] += t;
        __syncthreads();
    }
    if (tid < nblocks) g_bsumex[tid] = s[tid] - g_bsum[tid];
}

__global__ void k_scan3() {
    int i = blockIdx.x * blockDim.x + threadIdx.x;
    if (i >= NN) return;
    int off = g_off[i] + g_bsumex[i >> 10];
    g_off[i] = off;
    g_cur[i] = off;
}

__global__ void k_scatter(const int* __restrict__ ei) {
    int i = blockIdx.x * blockDim.x + threadIdx.x;
    if (i >= EP) return;
    int s, d;
    if (i < EE) { s = ei[i]; d = ei[EE + i]; }
    else        { s = d = i - EE; }
    int pos = atomicAdd(&g_cur[d], 1);
    g_esrc[pos] = s;
}

// ---------------- mma.sync bf16 GEMM ----------------
// CTA tile 128 x 128, 256 threads = 8 warps (4M x 2N), warp tile 32x64.
// 3-stage cp.async pipeline, K-chunk 64. 2 CTAs/SM.
// 2-term split: D = Ahi*Bhi + Alo*Bhi. Logical K = KLOG = 2K.
#define A_BYTES (128 * 64 * 2)   // 16KB
#define B_BYTES (128 * 64 * 2)   // 16KB
#define GEMM_SMEM (3 * (A_BYTES + B_BYTES))   // 96KB

template <int KLOG, int KB>
__global__ void __launch_bounds__(256, 2) k_gemm(int wsel,
                                                 const float* __restrict__ biasL,
                                                 const float* __restrict__ biasR) {
    extern __shared__ char smem[];
    const __nv_bfloat16* Wb = (wsel == 0) ? g_Wb0 : (wsel == 1) ? g_Wb1 : g_Wb2;
    const int tid = threadIdx.x;
    const int lane = tid & 31, wid = tid >> 5;
    const int m0 = blockIdx.x * 128;
    const int n0 = blockIdx.y * 128;
    const int wm = (wid & 3) * 32;
    const int wn = (wid >> 2) * 64;

    uint32_t sbase = smem_to_u32(smem);

    float acc[2][8][4];
    #pragma unroll
    for (int mt = 0; mt < 2; mt++)
        #pragma unroll
        for (int nt = 0; nt < 8; nt++)
            #pragma unroll
            for (int q = 0; q < 4; q++) acc[mt][nt][q] = 0.f;

    constexpr int NT = KLOG / 64;

    auto issue = [&](int slot, int c) {
        uint32_t ab = sbase + slot * A_BYTES;
        uint32_t bb = sbase + 3 * A_BYTES + slot * B_BYTES;
        int ka = c * 64;
        int kb = (c * 64) & (KB - 1);
        #pragma unroll
        for (int i = 0; i < 4; i++) {
            int chunk = tid + i * 256;
            int row = chunk >> 3, seg = chunk & 7;
            int sw = SMEM_SWIZZLE_128B(row * 128 + seg * 16);
            bool ok = (m0 + row) < NN;
            int grow = ok ? (m0 + row) : 0;
            cp_async16(ab + sw, &g_Ab[(size_t)grow * KLOG + ka + seg * 8], ok);
        }
        #pragma unroll
        for (int i = 0; i < 4; i++) {
            int chunk = tid + i * 256;
            int row = chunk >> 3, seg = chunk & 7;
            int sw = SMEM_SWIZZLE_128B(row * 128 + seg * 16);
            cp_async16(bb + sw, &Wb[(size_t)(n0 + row) * KB + kb + seg * 8], true);
        }
        asm volatile("cp.async.commit_group;" ::: "memory");
    };

    issue(0, 0);
    issue(1, 1);

    for (int t = 0; t < NT; t++) {
        if (t + 1 < NT) cp_async_wait<1>(); else cp_async_wait<0>();
        __syncthreads();
        if (t + 2 < NT) issue((t + 2) % 3, t + 2);

        int slot = t % 3;
        uint32_t ab = sbase + slot * A_BYTES;
        uint32_t bb = sbase + 3 * A_BYTES + slot * B_BYTES;
        #pragma unroll
        for (int ks = 0; ks < 4; ks++) {
            int k16 = ks * 16;
            uint32_t a[2][4];
            #pragma unroll
            for (int mt = 0; mt < 2; mt++) {
                int row = wm + mt * 16 + (lane & 15);
                int col = k16 + (lane >> 4) * 8;
                ldsm_x4(a[mt], ab + SMEM_SWIZZLE_128B(row * 128 + col * 2));
            }
            uint32_t b[4][4];
            #pragma unroll
            for (int nt = 0; nt < 4; nt++) {
                int row = wn + nt * 16 + (lane & 7) + ((lane >> 4) << 3);
                int col = k16 + ((lane >> 3) & 1) * 8;
                ldsm_x4(b[nt], bb + SMEM_SWIZZLE_128B(row * 128 + col * 2));
            }
            #pragma unroll
            for (int mt = 0; mt < 2; mt++)
                #pragma unroll
                for (int nt = 0; nt < 8; nt++)
                    mma16816(acc[mt][nt], a[mt], &b[nt >> 1][(nt & 1) * 2]);
        }
    }

    // epilogue: bias add + split XL/XR
    bool halfR = (n0 + wn) >= 256;
    float* outp = halfR ? g_XR : g_XL;
    const float* bias = halfR ? biasR : biasL;
    int cb = n0 + wn - (halfR ? 256 : 0);
    #pragma unroll
    for (int mt = 0; mt < 2; mt++) {
        int r0 = m0 + wm + mt * 16 + (lane >> 2);
        #pragma unroll
        for (int nt = 0; nt < 8; nt++) {
            int c = cb + nt * 8 + (lane & 3) * 2;
            float b0 = bias[c], b1 = bias[c + 1];
            if (r0 < NN)
                *(float2*)&outp[(size_t)r0 * HC + c] =
                    make_float2(acc[mt][nt][0] + b0, acc[mt][nt][1] + b1);
            if (r0 + 8 < NN)
                *(float2*)&outp[(size_t)(r0 + 8) * HC + c] =
                    make_float2(acc[mt][nt][2] + b0, acc[mt][nt][3] + b1);
        }
    }
}

// ---------------- warp-per-node edge softmax + aggregation (round-8/12 form) ----------------
// PACK=true: write relu(h) as bf16 [hi|lo] (stride 512) directly to g_Ab.
// PACK=false: write h (fp32) to g_H (feeds pooling).
template <bool PACK>
__global__ void k_agg(const float* __restrict__ att, const float* __restrict__ bias) {
    int gt = blockIdx.x * blockDim.x + threadIdx.x;
    int node = gt >> 5;
    int lane = gt & 31;
    if (node >= NN) return;

    int fb = lane * 8;

    float4 x0 = *(const float4*)&g_XR[(size_t)node * HC + fb];
    float4 x1 = *(const float4*)&g_XR[(size_t)node * HC + fb + 4];
    float xr[8] = {x0.x, x0.y, x0.z, x0.w, x1.x, x1.y, x1.z, x1.w};
    float4 a0 = *(const float4*)&att[fb];
    float4 a1 = *(const float4*)&att[fb + 4];
    float at[8] = {a0.x, a0.y, a0.z, a0.w, a1.x, a1.y, a1.z, a1.w};

    float acc[8];
    #pragma unroll
    for (int j = 0; j < 8; j++) acc[j] = 0.f;
    float m = -CUDART_INF_F, den = 0.f;

    int st = g_off[node];
    int en = st + g_deg[node];

    int e = st;
    for (; e + 1 < en; e += 2) {
        int s0 = g_esrc[e];
        int s1 = g_esrc[e + 1];
        float4 u0 = *(const float4*)&g_XL[(size_t)s0 * HC + fb];
        float4 u1 = *(const float4*)&g_XL[(size_t)s0 * HC + fb + 4];
        float4 w0v = *(const float4*)&g_XL[(size_t)s1 * HC + fb];
        float4 w1v = *(const float4*)&g_XL[(size_t)s1 * HC + fb + 4];
        float v0[8] = {u0.x, u0.y, u0.z, u0.w, u1.x, u1.y, u1.z, u1.w};
        float v1[8] = {w0v.x, w0v.y, w0v.z, w0v.w, w1v.x, w1v.y, w1v.z, w1v.w};

        float p0 = 0.f, p1 = 0.f;
        #pragma unroll
        for (int j = 0; j < 8; j++) {
            float t0 = v0[j] + xr[j];
            float t1 = v1[j] + xr[j];
            t0 = (t0 > 0.f) ? t0 : 0.2f * t0;
            t1 = (t1 > 0.f) ? t1 : 0.2f * t1;
            p0 = fmaf(t0, at[j], p0);
            p1 = fmaf(t1, at[j], p1);
        }
        #pragma unroll
        for (int o = 1; o <= 4; o <<= 1) {
            p0 += __shfl_xor_sync(0xFFFFFFFFu, p0, o);
            p1 += __shfl_xor_sync(0xFFFFFFFFu, p1, o);
        }

        float mn = fmaxf(m, fmaxf(p0, p1));
        float sc = __expf(m - mn);
        float w0 = __expf(p0 - mn);
        float w1 = __expf(p1 - mn);
        den = fmaf(den, sc, w0 + w1);
        #pragma unroll
        for (int j = 0; j < 8; j++)
            acc[j] = fmaf(acc[j], sc, fmaf(w0, v0[j], w1 * v1[j]));
        m = mn;
    }
    if (e < en) {
        int s = g_esrc[e];
        float4 u0 = *(const float4*)&g_XL[(size_t)s * HC + fb];
        float4 u1 = *(const float4*)&g_XL[(size_t)s * HC + fb + 4];
        float v[8] = {u0.x, u0.y, u0.z, u0.w, u1.x, u1.y, u1.z, u1.w};
        float ps = 0.f;
        #pragma unroll
        for (int j = 0; j < 8; j++) {
            float t = v[j] + xr[j];
            t = (t > 0.f) ? t : 0.2f * t;
            ps = fmaf(t, at[j], ps);
        }
        #pragma unroll
        for (int o = 1; o <= 4; o <<= 1)
            ps += __shfl_xor_sync(0xFFFFFFFFu, ps, o);
        float mn = fmaxf(m, ps);
        float sc = __expf(m - mn);
        float w = __expf(ps - mn);
        den = fmaf(den, sc, w);
        #pragma unroll
        for (int j = 0; j < 8; j++) acc[j] = fmaf(acc[j], sc, w * v[j]);
        m = mn;
    }

    float inv = 1.f / den;
    float4 bb0 = *(const float4*)&bias[fb];
    float4 bb1 = *(const float4*)&bias[fb + 4];
    float bs[8] = {bb0.x, bb0.y, bb0.z, bb0.w, bb1.x, bb1.y, bb1.z, bb1.w};
    float o[8];
    #pragma unroll
    for (int j = 0; j < 8; j++) o[j] = fmaf(acc[j], inv, bs[j]);

    if (PACK) {
        uint32_t hw[4], lw[4];
        #pragma unroll
        for (int i = 0; i < 4; i++) {
            float r0 = fmaxf(o[2 * i], 0.f);
            float r1 = fmaxf(o[2 * i + 1], 0.f);
            __nv_bfloat16 h0 = __float2bfloat16(r0);
            __nv_bfloat16 h1 = __float2bfloat16(r1);
            __nv_bfloat16 l0 = __float2bfloat16(r0 - __bfloat162float(h0));
            __nv_bfloat16 l1 = __float2bfloat16(r1 - __bfloat162float(h1));
            hw[i] = (uint32_t)__bfloat16_as_ushort(h0) |
                    ((uint32_t)__bfloat16_as_ushort(h1) << 16);
            lw[i] = (uint32_t)__bfloat16_as_ushort(l0) |
                    ((uint32_t)__bfloat16_as_ushort(l1) << 16);
        }
        size_t base = (size_t)node * 512 + fb;
        *(uint4*)&g_Ab[base]       = make_uint4(hw[0], hw[1], hw[2], hw[3]);
        *(uint4*)&g_Ab[base + 256] = make_uint4(lw[0], lw[1], lw[2], lw[3]);
    } else {
        *(float4*)&g_H[(size_t)node * HC + fb] =
            make_float4(o[0], o[1], o[2], o[3]);
        *(float4*)&g_H[(size_t)node * HC + fb + 4] =
            make_float4(o[4], o[5], o[6], o[7]);
    }
}

// ---------------- pooling ----------------
__global__ void k_pool(const int* __restrict__ batch) {
    int f = threadIdx.x;
    int n0 = blockIdx.x * 256;
    int n1 = min(n0 + 256, NN);
    int curg = -1;
    float s = 0.f, mx = -CUDART_INF_F;
    for (int n = n0; n < n1; n++) {
        int g = batch[n];
        float v = g_H[(size_t)n * HC + f];
        if (g != curg) {
            if (curg >= 0) {
                atomicAdd(&g_psum[curg * HC + f], s);
                atomicMax(&g_pmax[curg * HC + f], fkey(mx));
            }
            curg = g; s = 0.f; mx = -CUDART_INF_F;
        }
        s += v;
        mx = fmaxf(mx, v);
    }
    if (curg >= 0) {
        atomicAdd(&g_psum[curg * HC + f], s);
        atomicMax(&g_pmax[curg * HC + f], fkey(mx));
    }
}

// ---------------- classifier + softmax ----------------
__global__ void k_final(const float* __restrict__ Wout, const float* __restrict__ bout,
                        float* __restrict__ out) {
    int g = threadIdx.x;
    if (g >= NG) return;
    float c = (float)max(g_cnt[g], 1);
    float inv_c = 1.f / c;
    float l0 = bout[0], l1 = bout[1], l2 = bout[2];
    for (int f = 0; f < HC; f++) {
        float p = g_psum[g * HC + f] * inv_c + fdekey(g_pmax[g * HC + f]);
        l0 = fmaf(p, Wout[f * NCLS + 0], l0);
        l1 = fmaf(p, Wout[f * NCLS + 1], l1);
        l2 = fmaf(p, Wout[f * NCLS + 2], l2);
    }
    float mx = fmaxf(l0, fmaxf(l1, l2));
    float e0 = __expf(l0 - mx), e1 = __expf(l1 - mx), e2 = __expf(l2 - mx);
    float inv = 1.f / (e0 + e1 + e2);
    out[g * NCLS + 0] = e0 * inv;
    out[g * NCLS + 1] = e1 * inv;
    out[g * NCLS + 2] = e2 * inv;
}

// ---------------- launch ----------------
extern "C" void kernel_launch(void* const* d_in, const int* in_sizes, int n_in,
                              void* d_out, int out_size) {
    const float* x     = (const float*)d_in[0];
    const int*   ei    = (const int*)d_in[1];
    const int*   batch = (const int*)d_in[2];
    const float* Wl[3]   = {(const float*)d_in[3],  (const float*)d_in[9],  (const float*)d_in[15]};
    const float* bl[3]   = {(const float*)d_in[4],  (const float*)d_in[10], (const float*)d_in[16]};
    const float* Wr[3]   = {(const float*)d_in[5],  (const float*)d_in[11], (const float*)d_in[17]};
    const float* br[3]   = {(const float*)d_in[6],  (const float*)d_in[12], (const float*)d_in[18]};
    const float* att[3]  = {(const float*)d_in[7],  (const float*)d_in[13], (const float*)d_in[19]};
    const float* bias[3] = {(const float*)d_in[8],  (const float*)d_in[14], (const float*)d_in[20]};
    const float* Wout    = (const float*)d_in[21];
    const float* bout    = (const float*)d_in[22];
    float* out = (float*)d_out;

    (void)in_sizes; (void)n_in; (void)out_size;

    static bool attr_done = false;
    if (!attr_done) {
        cudaFuncSetAttribute((const void*)k_gemm<256, 128>,
                             cudaFuncAttributeMaxDynamicSharedMemorySize, GEMM_SMEM);
        cudaFuncSetAttribute((const void*)k_gemm<512, 256>,
                             cudaFuncAttributeMaxDynamicSharedMemorySize, GEMM_SMEM);
        attr_done = true;
    }

    dim3 ggrid((NN + 127) / 128, 4);
    int abl = (NN * 32 + 63) / 64;      // k_agg: 64 threads/block (2 warps) -> finest balance
    int ebl = (EP + 255) / 256;
    int sblocks = (NN + 1023) / 1024;   // 49

    // 1: fused convA | convW | init
    k_prep<<<PB_I, 256>>>(x, Wl[0], Wr[0], Wl[1], Wr[1], Wl[2], Wr[2]);
    // 2: deg histogram + graph counts (after init)
    k_deg<<<ebl, 256>>>(ei, batch);
    // 3: block-local scan
    k_scan1<<<sblocks, 1024>>>();
    // 4: layer-0 GEMM  <-- ncu capture slot (sentinel)
    k_gemm<256, 128><<<ggrid, 256, GEMM_SMEM>>>(0, bl[0], br[0]);
    // 5-6: finish scan
    k_scan2<<<1, 64>>>(sblocks);
    k_scan3<<<(NN + 255) / 256, 256>>>();
    // 7: scatter
    k_scatter<<<ebl, 256>>>(ei);
    // 8: layer-0 aggregation (packs relu(h) -> g_Ab)
    k_agg<true><<<abl, 64>>>(att[0], bias[0]);
    // 9-10: layer 1
    k_gemm<512, 256><<<ggrid, 256, GEMM_SMEM>>>(1, bl[1], br[1]);
    k_agg<true><<<abl, 64>>>(att[1], bias[1]);
    // 11-12: layer 2
    k_gemm<512, 256><<<ggrid, 256, GEMM_SMEM>>>(2, bl[2], br[2]);
    k_agg<false><<<abl, 64>>>(att[2], bias[2]);
    // 13-14: pooling + classifier
    k_pool<<<(NN + 255) / 256, 256>>>(batch);
    k_final<<<1, 64>>>(Wout, bout, out);
}

// round 16
// speedup vs baseline: 1.1192x; 1.0267x over previous
#include <cuda_runtime.h>
#include <cuda_bf16.h>
#include <math_constants.h>
#include <cstdint>

// Problem constants (fixed by the dataset)
#define NN   50000
#define EE   600000
#define EP   (EE + NN)     // edges + self loops = 650000
#define FIN  128
#define HC   256           // H*C = 4*64
#define NG   64            // graphs
#define NCLS 3

#define SMEM_SWIZZLE_128B(b) ((b) ^ (((b) >> 3) & 0x70))

__device__ __forceinline__ uint32_t smem_to_u32(const void* p) {
    uint32_t a;
    asm("{ .reg .u64 t; cvta.to.shared.u64 t, %1; cvt.u32.u64 %0, t; }" : "=r"(a) : "l"(p));
    return a;
}
__device__ __forceinline__ void cp_async16(uint32_t dst, const void* src, bool pred) {
    int sz = pred ? 16 : 0;
    asm volatile("cp.async.cg.shared.global [%0], [%1], 16, %2;"
                 :: "r"(dst), "l"(src), "r"(sz) : "memory");
}
template <int N>
__device__ __forceinline__ void cp_async_wait() {
    asm volatile("cp.async.wait_group %0;" :: "n"(N) : "memory");
}
__device__ __forceinline__ void ldsm_x4(uint32_t* r, uint32_t addr) {
    asm volatile("ldmatrix.sync.aligned.m8n8.x4.shared.b16 {%0,%1,%2,%3}, [%4];"
                 : "=r"(r[0]), "=r"(r[1]), "=r"(r[2]), "=r"(r[3]) : "r"(addr));
}
__device__ __forceinline__ void mma16816(float* c, const uint32_t* a, const uint32_t* b) {
    asm volatile("mma.sync.aligned.m16n8k16.row.col.f32.bf16.bf16.f32 "
                 "{%0,%1,%2,%3}, {%4,%5,%6,%7}, {%8,%9}, {%0,%1,%2,%3};"
                 : "+f"(c[0]), "+f"(c[1]), "+f"(c[2]), "+f"(c[3])
                 : "r"(a[0]), "r"(a[1]), "r"(a[2]), "r"(a[3]), "r"(b[0]), "r"(b[1]));
}

// ---------------- device scratch (no allocation allowed) ----------------
__device__ float g_XL[(size_t)NN * HC];
__device__ float g_XR[(size_t)NN * HC];
__device__ float g_H [(size_t)NN * HC];
__device__ __align__(16) __nv_bfloat16 g_Ab[(size_t)NN * 512];  // A [hi|lo], stride 2K
__device__ __align__(16) __nv_bfloat16 g_Wb0[512 * 128];        // layer0 B = Whi only, [n][K]
__device__ __align__(16) __nv_bfloat16 g_Wb1[512 * 256];        // layer1 B = Whi only
__device__ __align__(16) __nv_bfloat16 g_Wb2[512 * 256];        // layer2 B = Whi only
__device__ int   g_deg[NN];
__device__ int   g_off[NN];
__device__ int   g_cur[NN];
__device__ int   g_esrc[EP];
__device__ int   g_bsum[64];
__device__ int   g_bsumex[64];
__device__ float    g_psum[NG * HC];
__device__ unsigned g_pmax[NG * HC];
__device__ int      g_cnt[NG];

__device__ __forceinline__ unsigned fkey(float f) {
    unsigned b = __float_as_uint(f);
    return (b & 0x80000000u) ? ~b : (b | 0x80000000u);
}
__device__ __forceinline__ float fdekey(unsigned u) {
    return (u & 0x80000000u) ? __uint_as_float(u & 0x7FFFFFFFu) : __uint_as_float(~u);
}

// ---------------- fused prologue: convA | convW | init ----------------
#define PB_A 6250                    // convA: NN*FIN/4 / 256
#define PB_W (PB_A + 1536)           // convW: 6 matrices x 256 blocks
#define PB_I (PB_W + 256)            // init
__global__ void k_prep(const float* __restrict__ x,
                       const float* __restrict__ Wl0, const float* __restrict__ Wr0,
                       const float* __restrict__ Wl1, const float* __restrict__ Wr1,
                       const float* __restrict__ Wl2, const float* __restrict__ Wr2) {
    int b = blockIdx.x, tid = threadIdx.x;
    if (b < PB_A) {
        // convA: fp32 -> bf16 [hi|lo], stride 256
        int i = b * 256 + tid;
        if (i >= NN * FIN / 4) return;
        int row = i >> 5, j = (i & 31) * 4;
        float4 v = ((const float4*)x)[i];
        __nv_bfloat16 hx = __float2bfloat16(v.x), hy = __float2bfloat16(v.y);
        __nv_bfloat16 hz = __float2bfloat16(v.z), hw = __float2bfloat16(v.w);
        __nv_bfloat162 h01(hx, hy), h23(hz, hw);
        __nv_bfloat162 l01(__float2bfloat16(v.x - __bfloat162float(hx)),
                           __float2bfloat16(v.y - __bfloat162float(hy)));
        __nv_bfloat162 l23(__float2bfloat16(v.z - __bfloat162float(hz)),
                           __float2bfloat16(v.w - __bfloat162float(hw)));
        size_t base = (size_t)row * 256;
        *(__nv_bfloat162*)&g_Ab[base + j]           = h01;
        *(__nv_bfloat162*)&g_Ab[base + j + 2]       = h23;
        *(__nv_bfloat162*)&g_Ab[base + 128 + j]     = l01;
        *(__nv_bfloat162*)&g_Ab[base + 128 + j + 2] = l23;
    } else if (b < PB_W) {
        // convW: W [K][256] fp32 -> dst[n][K] bf16 (hi)
        int bb = b - PB_A;
        int y = bb >> 8;
        int K = (y < 2) ? FIN : HC;
        int i = (bb & 255) * 256 + tid;
        if (i >= K * 256) return;
        const float* W;
        __nv_bfloat16* dst;
        switch (y) {
            case 0: W = Wl0; dst = g_Wb0; break;
            case 1: W = Wr0; dst = g_Wb0; break;
            case 2: W = Wl1; dst = g_Wb1; break;
            case 3: W = Wr1; dst = g_Wb1; break;
            case 4: W = Wl2; dst = g_Wb2; break;
            default: W = Wr2; dst = g_Wb2; break;
        }
        int nbase = (y & 1) * 256;
        int k = i >> 8, n = i & 255;
        dst[(size_t)(nbase + n) * K + k] = __float2bfloat16(W[i]);
    } else {
        // init: deg/psum/pmax/cnt
        int i = (b - PB_W) * 256 + tid;
        int stride = 256 * 256;
        for (int j = i; j < NN; j += stride) g_deg[j] = 0;
        for (int j = i; j < NG * HC; j += stride) { g_psum[j] = 0.f; g_pmax[j] = 0x007FFFFFu; }
        for (int j = i; j < NG; j += stride) g_cnt[j] = 0;
    }
}

// deg histogram + graph counts (after k_prep's init has completed)
__global__ void k_deg(const int* __restrict__ ei, const int* __restrict__ batch) {
    int i = blockIdx.x * blockDim.x + threadIdx.x;
    if (i < NN) atomicAdd(&g_cnt[batch[i]], 1);
    if (i >= EP) return;
    int d = (i < EE) ? ei[EE + i] : (i - EE);
    atomicAdd(&g_deg[d], 1);
}

// ---------------- 3-phase scan ----------------
__global__ void k_scan1() {
    __shared__ int wsum[32];
    int b = blockIdx.x, tid = threadIdx.x, lane = tid & 31, wid = tid >> 5;
    int i = b * 1024 + tid;
    int v = (i < NN) ? g_deg[i] : 0;
    int x = v;
    #pragma unroll
    for (int o = 1; o < 32; o <<= 1) {
        int t = __shfl_up_sync(0xFFFFFFFFu, x, o);
        if (lane >= o) x += t;
    }
    if (lane == 31) wsum[wid] = x;
    __syncthreads();
    if (wid == 0) {
        int orig = wsum[lane];
        int y = orig;
        #pragma unroll
        for (int o = 1; o < 32; o <<= 1) {
            int t = __shfl_up_sync(0xFFFFFFFFu, y, o);
            if (lane >= o) y += t;
        }
        wsum[lane] = y - orig;
    }
    __syncthreads();
    int incl = x + wsum[wid];
    if (i < NN) g_off[i] = incl - v;
    if (tid == 1023) g_bsum[b] = incl;
}

__global__ void k_scan2(int nblocks) {
    __shared__ int s[64];
    int tid = threadIdx.x;
    s[tid] = (tid < nblocks) ? g_bsum[tid] : 0;
    __syncthreads();
    #pragma unroll
    for (int o = 1; o < 64; o <<= 1) {
        int t = (tid >= o) ? s[tid - o] : 0;
        __syncthreads();
        s[tid] += t;
        __syncthreads();
    }
    if (tid < nblocks) g_bsumex[tid] = s[tid] - g_bsum[tid];
}

__global__ void k_scan3() {
    int i = blockIdx.x * blockDim.x + threadIdx.x;
    if (i >= NN) return;
    int off = g_off[i] + g_bsumex[i >> 10];
    g_off[i] = off;
    g_cur[i] = off;
}

__global__ void k_scatter(const int* __restrict__ ei) {
    int i = blockIdx.x * blockDim.x + threadIdx.x;
    if (i >= EP) return;
    int s, d;
    if (i < EE) { s = ei[i]; d = ei[EE + i]; }
    else        { s = d = i - EE; }
    int pos = atomicAdd(&g_cur[d], 1);
    g_esrc[pos] = s;
}

// ---------------- mma.sync bf16 GEMM ----------------
// CTA tile 128 x 128, 256 threads = 8 warps (4M x 2N), warp tile 32x64.
// 3-stage cp.async pipeline, K-chunk 64. 2 CTAs/SM.
// 2-term split: D = Ahi*Bhi + Alo*Bhi. Logical K = KLOG = 2K.
// Grid is (4, 391): blockIdx.x = N tile (fast), blockIdx.y = M tile, so the
// 4 launch-adjacent CTAs share one A tile -> A read from DRAM once, L2 3x.
#define A_BYTES (128 * 64 * 2)   // 16KB
#define B_BYTES (128 * 64 * 2)   // 16KB
#define GEMM_SMEM (3 * (A_BYTES + B_BYTES))   // 96KB

template <int KLOG, int KB>
__global__ void __launch_bounds__(256, 2) k_gemm(int wsel,
                                                 const float* __restrict__ biasL,
                                                 const float* __restrict__ biasR) {
    extern __shared__ char smem[];
    const __nv_bfloat16* Wb = (wsel == 0) ? g_Wb0 : (wsel == 1) ? g_Wb1 : g_Wb2;
    const int tid = threadIdx.x;
    const int lane = tid & 31, wid = tid >> 5;
    const int m0 = blockIdx.y * 128;   // M on slow axis
    const int n0 = blockIdx.x * 128;   // N on fast axis -> A-tile sharing
    const int wm = (wid & 3) * 32;
    const int wn = (wid >> 2) * 64;

    uint32_t sbase = smem_to_u32(smem);

    float acc[2][8][4];
    #pragma unroll
    for (int mt = 0; mt < 2; mt++)
        #pragma unroll
        for (int nt = 0; nt < 8; nt++)
            #pragma unroll
            for (int q = 0; q < 4; q++) acc[mt][nt][q] = 0.f;

    constexpr int NT = KLOG / 64;

    auto issue = [&](int slot, int c) {
        uint32_t ab = sbase + slot * A_BYTES;
        uint32_t bb = sbase + 3 * A_BYTES + slot * B_BYTES;
        int ka = c * 64;
        int kb = (c * 64) & (KB - 1);
        #pragma unroll
        for (int i = 0; i < 4; i++) {
            int chunk = tid + i * 256;
            int row = chunk >> 3, seg = chunk & 7;
            int sw = SMEM_SWIZZLE_128B(row * 128 + seg * 16);
            bool ok = (m0 + row) < NN;
            int grow = ok ? (m0 + row) : 0;
            cp_async16(ab + sw, &g_Ab[(size_t)grow * KLOG + ka + seg * 8], ok);
        }
        #pragma unroll
        for (int i = 0; i < 4; i++) {
            int chunk = tid + i * 256;
            int row = chunk >> 3, seg = chunk & 7;
            int sw = SMEM_SWIZZLE_128B(row * 128 + seg * 16);
            cp_async16(bb + sw, &Wb[(size_t)(n0 + row) * KB + kb + seg * 8], true);
        }
        asm volatile("cp.async.commit_group;" ::: "memory");
    };

    issue(0, 0);
    issue(1, 1);

    for (int t = 0; t < NT; t++) {
        if (t + 1 < NT) cp_async_wait<1>(); else cp_async_wait<0>();
        __syncthreads();
        if (t + 2 < NT) issue((t + 2) % 3, t + 2);

        int slot = t % 3;
        uint32_t ab = sbase + slot * A_BYTES;
        uint32_t bb = sbase + 3 * A_BYTES + slot * B_BYTES;
        #pragma unroll
        for (int ks = 0; ks < 4; ks++) {
            int k16 = ks * 16;
            uint32_t a[2][4];
            #pragma unroll
            for (int mt = 0; mt < 2; mt++) {
                int row = wm + mt * 16 + (lane & 15);
                int col = k16 + (lane >> 4) * 8;
                ldsm_x4(a[mt], ab + SMEM_SWIZZLE_128B(row * 128 + col * 2));
            }
            uint32_t b[4][4];
            #pragma unroll
            for (int nt = 0; nt < 4; nt++) {
                int row = wn + nt * 16 + (lane & 7) + ((lane >> 4) << 3);
                int col = k16 + ((lane >> 3) & 1) * 8;
                ldsm_x4(b[nt], bb + SMEM_SWIZZLE_128B(row * 128 + col * 2));
            }
            #pragma unroll
            for (int mt = 0; mt < 2; mt++)
                #pragma unroll
                for (int nt = 0; nt < 8; nt++)
                    mma16816(acc[mt][nt], a[mt], &b[nt >> 1][(nt & 1) * 2]);
        }
    }

    // epilogue: bias add + split XL/XR
    bool halfR = (n0 + wn) >= 256;
    float* outp = halfR ? g_XR : g_XL;
    const float* bias = halfR ? biasR : biasL;
    int cb = n0 + wn - (halfR ? 256 : 0);
    #pragma unroll
    for (int mt = 0; mt < 2; mt++) {
        int r0 = m0 + wm + mt * 16 + (lane >> 2);
        #pragma unroll
        for (int nt = 0; nt < 8; nt++) {
            int c = cb + nt * 8 + (lane & 3) * 2;
            float b0 = bias[c], b1 = bias[c + 1];
            if (r0 < NN)
                *(float2*)&outp[(size_t)r0 * HC + c] =
                    make_float2(acc[mt][nt][0] + b0, acc[mt][nt][1] + b1);
            if (r0 + 8 < NN)
                *(float2*)&outp[(size_t)(r0 + 8) * HC + c] =
                    make_float2(acc[mt][nt][2] + b0, acc[mt][nt][3] + b1);
        }
    }
}

// ---------------- warp-per-node edge softmax + aggregation (round-8/12 form) ----------------
// PACK=true: write relu(h) as bf16 [hi|lo] (stride 512) directly to g_Ab.
// PACK=false: write h (fp32) to g_H (feeds pooling).
template <bool PACK>
__global__ void k_agg(const float* __restrict__ att, const float* __restrict__ bias) {
    int gt = blockIdx.x * blockDim.x + threadIdx.x;
    int node = gt >> 5;
    int lane = gt & 31;
    if (node >= NN) return;

    int fb = lane * 8;

    float4 x0 = *(const float4*)&g_XR[(size_t)node * HC + fb];
    float4 x1 = *(const float4*)&g_XR[(size_t)node * HC + fb + 4];
    float xr[8] = {x0.x, x0.y, x0.z, x0.w, x1.x, x1.y, x1.z, x1.w};
    float4 a0 = *(const float4*)&att[fb];
    float4 a1 = *(const float4*)&att[fb + 4];
    float at[8] = {a0.x, a0.y, a0.z, a0.w, a1.x, a1.y, a1.z, a1.w};

    float acc[8];
    #pragma unroll
    for (int j = 0; j < 8; j++) acc[j] = 0.f;
    float m = -CUDART_INF_F, den = 0.f;

    int st = g_off[node];
    int en = st + g_deg[node];

    int e = st;
    for (; e + 1 < en; e += 2) {
        int s0 = g_esrc[e];
        int s1 = g_esrc[e + 1];
        float4 u0 = *(const float4*)&g_XL[(size_t)s0 * HC + fb];
        float4 u1 = *(const float4*)&g_XL[(size_t)s0 * HC + fb + 4];
        float4 w0v = *(const float4*)&g_XL[(size_t)s1 * HC + fb];
        float4 w1v = *(const float4*)&g_XL[(size_t)s1 * HC + fb + 4];
        float v0[8] = {u0.x, u0.y, u0.z, u0.w, u1.x, u1.y, u1.z, u1.w};
        float v1[8] = {w0v.x, w0v.y, w0v.z, w0v.w, w1v.x, w1v.y, w1v.z, w1v.w};

        float p0 = 0.f, p1 = 0.f;
        #pragma unroll
        for (int j = 0; j < 8; j++) {
            float t0 = v0[j] + xr[j];
            float t1 = v1[j] + xr[j];
            t0 = (t0 > 0.f) ? t0 : 0.2f * t0;
            t1 = (t1 > 0.f) ? t1 : 0.2f * t1;
            p0 = fmaf(t0, at[j], p0);
            p1 = fmaf(t1, at[j], p1);
        }
        #pragma unroll
        for (int o = 1; o <= 4; o <<= 1) {
            p0 += __shfl_xor_sync(0xFFFFFFFFu, p0, o);
            p1 += __shfl_xor_sync(0xFFFFFFFFu, p1, o);
        }

        float mn = fmaxf(m, fmaxf(p0, p1));
        float sc = __expf(m - mn);
        float w0 = __expf(p0 - mn);
        float w1 = __expf(p1 - mn);
        den = fmaf(den, sc, w0 + w1);
        #pragma unroll
        for (int j = 0; j < 8; j++)
            acc[j] = fmaf(acc[j], sc, fmaf(w0, v0[j], w1 * v1[j]));
        m = mn;
    }
    if (e < en) {
        int s = g_esrc[e];
        float4 u0 = *(const float4*)&g_XL[(size_t)s * HC + fb];
        float4 u1 = *(const float4*)&g_XL[(size_t)s * HC + fb + 4];
        float v[8] = {u0.x, u0.y, u0.z, u0.w, u1.x, u1.y, u1.z, u1.w};
        float ps = 0.f;
        #pragma unroll
        for (int j = 0; j < 8; j++) {
            float t = v[j] + xr[j];
            t = (t > 0.f) ? t : 0.2f * t;
            ps = fmaf(t, at[j], ps);
        }
        #pragma unroll
        for (int o = 1; o <= 4; o <<= 1)
            ps += __shfl_xor_sync(0xFFFFFFFFu, ps, o);
        float mn = fmaxf(m, ps);
        float sc = __expf(m - mn);
        float w = __expf(ps - mn);
        den = fmaf(den, sc, w);
        #pragma unroll
        for (int j = 0; j < 8; j++) acc[j] = fmaf(acc[j], sc, w * v[j]);
        m = mn;
    }

    float inv = 1.f / den;
    float4 bb0 = *(const float4*)&bias[fb];
    float4 bb1 = *(const float4*)&bias[fb + 4];
    float bs[8] = {bb0.x, bb0.y, bb0.z, bb0.w, bb1.x, bb1.y, bb1.z, bb1.w};
    float o[8];
    #pragma unroll
    for (int j = 0; j < 8; j++) o[j] = fmaf(acc[j], inv, bs[j]);

    if (PACK) {
        uint32_t hw[4], lw[4];
        #pragma unroll
        for (int i = 0; i < 4; i++) {
            float r0 = fmaxf(o[2 * i], 0.f);
            float r1 = fmaxf(o[2 * i + 1], 0.f);
            __nv_bfloat16 h0 = __float2bfloat16(r0);
            __nv_bfloat16 h1 = __float2bfloat16(r1);
            __nv_bfloat16 l0 = __float2bfloat16(r0 - __bfloat162float(h0));
            __nv_bfloat16 l1 = __float2bfloat16(r1 - __bfloat162float(h1));
            hw[i] = (uint32_t)__bfloat16_as_ushort(h0) |
                    ((uint32_t)__bfloat16_as_ushort(h1) << 16);
            lw[i] = (uint32_t)__bfloat16_as_ushort(l0) |
                    ((uint32_t)__bfloat16_as_ushort(l1) << 16);
        }
        size_t base = (size_t)node * 512 + fb;
        *(uint4*)&g_Ab[base]       = make_uint4(hw[0], hw[1], hw[2], hw[3]);
        *(uint4*)&g_Ab[base + 256] = make_uint4(lw[0], lw[1], lw[2], lw[3]);
    } else {
        *(float4*)&g_H[(size_t)node * HC + fb] =
            make_float4(o[0], o[1], o[2], o[3]);
        *(float4*)&g_H[(size_t)node * HC + fb + 4] =
            make_float4(o[4], o[5], o[6], o[7]);
    }
}

// ---------------- pooling ----------------
__global__ void k_pool(const int* __restrict__ batch) {
    int f = threadIdx.x;
    int n0 = blockIdx.x * 256;
    int n1 = min(n0 + 256, NN);
    int curg = -1;
    float s = 0.f, mx = -CUDART_INF_F;
    for (int n = n0; n < n1; n++) {
        int g = batch[n];
        float v = g_H[(size_t)n * HC + f];
        if (g != curg) {
            if (curg >= 0) {
                atomicAdd(&g_psum[curg * HC + f], s);
                atomicMax(&g_pmax[curg * HC + f], fkey(mx));
            }
            curg = g; s = 0.f; mx = -CUDART_INF_F;
        }
        s += v;
        mx = fmaxf(mx, v);
    }
    if (curg >= 0) {
        atomicAdd(&g_psum[curg * HC + f], s);
        atomicMax(&g_pmax[curg * HC + f], fkey(mx));
    }
}

// ---------------- classifier + softmax ----------------
__global__ void k_final(const float* __restrict__ Wout, const float* __restrict__ bout,
                        float* __restrict__ out) {
    int g = threadIdx.x;
    if (g >= NG) return;
    float c = (float)max(g_cnt[g], 1);
    float inv_c = 1.f / c;
    float l0 = bout[0], l1 = bout[1], l2 = bout[2];
    for (int f = 0; f < HC; f++) {
        float p = g_psum[g * HC + f] * inv_c + fdekey(g_pmax[g * HC + f]);
        l0 = fmaf(p, Wout[f * NCLS + 0], l0);
        l1 = fmaf(p, Wout[f * NCLS + 1], l1);
        l2 = fmaf(p, Wout[f * NCLS + 2], l2);
    }
    float mx = fmaxf(l0, fmaxf(l1, l2));
    float e0 = __expf(l0 - mx), e1 = __expf(l1 - mx), e2 = __expf(l2 - mx);
    float inv = 1.f / (e0 + e1 + e2);
    out[g * NCLS + 0] = e0 * inv;
    out[g * NCLS + 1] = e1 * inv;
    out[g * NCLS + 2] = e2 * inv;
}

// ---------------- launch ----------------
extern "C" void kernel_launch(void* const* d_in, const int* in_sizes, int n_in,
                              void* d_out, int out_size) {
    const float* x     = (const float*)d_in[0];
    const int*   ei    = (const int*)d_in[1];
    const int*   batch = (const int*)d_in[2];
    const float* Wl[3]   = {(const float*)d_in[3],  (const float*)d_in[9],  (const float*)d_in[15]};
    const float* bl[3]   = {(const float*)d_in[4],  (const float*)d_in[10], (const float*)d_in[16]};
    const float* Wr[3]   = {(const float*)d_in[5],  (const float*)d_in[11], (const float*)d_in[17]};
    const float* br[3]   = {(const float*)d_in[6],  (const float*)d_in[12], (const float*)d_in[18]};
    const float* att[3]  = {(const float*)d_in[7],  (const float*)d_in[13], (const float*)d_in[19]};
    const float* bias[3] = {(const float*)d_in[8],  (const float*)d_in[14], (const float*)d_in[20]};
    const float* Wout    = (const float*)d_in[21];
    const float* bout    = (const float*)d_in[22];
    float* out = (float*)d_out;

    (void)in_sizes; (void)n_in; (void)out_size;

    static bool attr_done = false;
    if (!attr_done) {
        cudaFuncSetAttribute((const void*)k_gemm<256, 128>,
                             cudaFuncAttributeMaxDynamicSharedMemorySize, GEMM_SMEM);
        cudaFuncSetAttribute((const void*)k_gemm<512, 256>,
                             cudaFuncAttributeMaxDynamicSharedMemorySize, GEMM_SMEM);
        attr_done = true;
    }

    dim3 ggrid(4, (NN + 127) / 128);    // N fast, M slow -> A-tile L2 sharing
    int abl = (NN * 32 + 63) / 64;      // k_agg: 64 threads/block (2 warps)
    int ebl = (EP + 255) / 256;
    int sblocks = (NN + 1023) / 1024;   // 49

    // 1: fused convA | convW | init
    k_prep<<<PB_I, 256>>>(x, Wl[0], Wr[0], Wl[1], Wr[1], Wl[2], Wr[2]);
    // 2: deg histogram + graph counts (after init)
    k_deg<<<ebl, 256>>>(ei, batch);
    // 3: block-local scan
    k_scan1<<<sblocks, 1024>>>();
    // 4: layer-0 GEMM  <-- ncu capture slot (sentinel)
    k_gemm<256, 128><<<ggrid, 256, GEMM_SMEM>>>(0, bl[0], br[0]);
    // 5-6: finish scan
    k_scan2<<<1, 64>>>(sblocks);
    k_scan3<<<(NN + 255) / 256, 256>>>();
    // 7: scatter
    k_scatter<<<ebl, 256>>>(ei);
    // 8: layer-0 aggregation (packs relu(h) -> g_Ab)
    k_agg<true><<<abl, 64>>>(att[0], bias[0]);
    // 9-10: layer 1
    k_gemm<512, 256><<<ggrid, 256, GEMM_SMEM>>>(1, bl[1], br[1]);
    k_agg<true><<<abl, 64>>>(att[1], bias[1]);
    // 11-12: layer 2
    k_gemm<512, 256><<<ggrid, 256, GEMM_SMEM>>>(2, bl[2], br[2]);
    k_agg<false><<<abl, 64>>>(att[2], bias[2]);
    // 13-14: pooling + classifier
    k_pool<<<(NN + 255) / 256, 256>>>(batch);
    k_final<<<1, 64>>>(Wout, bout, out);
}